// round 12
// baseline (speedup 1.0000x reference)
#include <cuda_runtime.h>
#include <cuda.h>
#include <cuda_fp16.h>
#include <math.h>
#include <stdint.h>

#define BB 4
#define LL 2048
#define DD 1024
#define HH 16
#define DHH 64
#define NTOK (BB*LL)   // 8192 rows
#define D3  (3*DD)     // 3072

// ---------------- scratch (device globals; no allocation allowed) ----------------
__device__ __align__(16) __half g_h   [NTOK*DD];
__device__ __align__(16) __half g_qkv [NTOK*D3];
__device__ __align__(16) __half g_ln2 [NTOK*DD];
__device__ __align__(16) __half g_mlp [NTOK*DD];
__device__ __align__(16) __half g_wqkv[3*DD*DD];
__device__ __align__(16) __half g_w1  [DD*DD];
__device__ __align__(16) __half g_w2  [DD*DD];
__device__ __align__(16) float  g_res [NTOK*DD];
__device__ __align__(16) float  g_bqkv[D3];

// ============================ helpers ============================
__device__ __forceinline__ uint32_t smem_u32(const void* p) {
    uint32_t a;
    asm("{ .reg .u64 t; cvta.to.shared.u64 t, %1; cvt.u32.u64 %0, t; }" : "=r"(a) : "l"(p));
    return a;
}
__device__ __forceinline__ void mma_f16(float* c, const uint32_t* a, const uint32_t* b) {
    asm volatile(
        "mma.sync.aligned.m16n8k16.row.col.f32.f16.f16.f32 "
        "{%0,%1,%2,%3}, {%4,%5,%6,%7}, {%8,%9}, {%0,%1,%2,%3};"
        : "+f"(c[0]), "+f"(c[1]), "+f"(c[2]), "+f"(c[3])
        : "r"(a[0]), "r"(a[1]), "r"(a[2]), "r"(a[3]), "r"(b[0]), "r"(b[1]));
}
// fp16-accumulate variant: c = 2 regs (4 halfs)
__device__ __forceinline__ void mma_f16h(uint32_t* c, const uint32_t* a, const uint32_t* b) {
    asm volatile(
        "mma.sync.aligned.m16n8k16.row.col.f16.f16.f16.f16 "
        "{%0,%1}, {%2,%3,%4,%5}, {%6,%7}, {%0,%1};"
        : "+r"(c[0]), "+r"(c[1])
        : "r"(a[0]), "r"(a[1]), "r"(a[2]), "r"(a[3]), "r"(b[0]), "r"(b[1]));
}
__device__ __forceinline__ void ldsm_x4(uint32_t* r, uint32_t addr) {
    asm volatile("ldmatrix.sync.aligned.m8n8.x4.shared.b16 {%0,%1,%2,%3}, [%4];"
        : "=r"(r[0]), "=r"(r[1]), "=r"(r[2]), "=r"(r[3]) : "r"(addr));
}
__device__ __forceinline__ void ldsm_x4_t(uint32_t* r, uint32_t addr) {
    asm volatile("ldmatrix.sync.aligned.m8n8.x4.trans.shared.b16 {%0,%1,%2,%3}, [%4];"
        : "=r"(r[0]), "=r"(r[1]), "=r"(r[2]), "=r"(r[3]) : "r"(addr));
}
__device__ __forceinline__ void cp16(uint32_t dst, const void* src) {
    asm volatile("cp.async.cg.shared.global [%0], [%1], 16;" :: "r"(dst), "l"(src));
}
#define CP_COMMIT() asm volatile("cp.async.commit_group;" ::: "memory")
#define CP_WAIT0()  asm volatile("cp.async.wait_group 0;" ::: "memory")

// ============ fp16 GEMM, fp32 accum ============
#define GS_STRIDE 40
#define GT_BYTES  (128*GS_STRIDE*2)      // 10240
#define GSTAGE    (2*GT_BYTES)
#define HGEMM_SMEM (2*GSTAGE)            // 40960

template<int ACT, bool RES, int OUTM>
__global__ void __launch_bounds__(256, 2)
hgemm_kernel(const __half* __restrict__ A, const __half* __restrict__ B,
             const float* __restrict__ bias, const float* __restrict__ res,
             float* __restrict__ Cf, __half* __restrict__ Ch,
             int M, int N, int K)
{
    extern __shared__ char dsm[];
    const uint32_t sb = smem_u32(dsm);

    const int tid  = threadIdx.x;
    const int wid  = tid >> 5;
    const int lane = tid & 31;
    const int wm   = wid >> 2;
    const int wn   = wid & 3;
    const int row0 = blockIdx.y * 128;
    const int col0 = blockIdx.x * 128;

    float acc[4][4][4];
    #pragma unroll
    for (int i = 0; i < 4; i++)
        #pragma unroll
        for (int j = 0; j < 4; j++)
            #pragma unroll
            for (int q = 0; q < 4; q++) acc[i][j][q] = 0.f;

    const uint32_t aoff = (uint32_t)(((lane & 15) * GS_STRIDE + ((lane >> 4) & 1) * 8) * 2);
    const int nkt = K / 32;

    auto load_stage = [&](int i, int buf) {
        uint32_t s0 = sb + (uint32_t)buf * GSTAGE;
        int kt = i * 32;
        #pragma unroll
        for (int u = 0; u < 2; u++) {
            int c   = tid + u * 256;
            int row = c >> 2;
            int ch  = c & 3;
            uint32_t so = (uint32_t)(row * (GS_STRIDE * 2) + ch * 16);
            cp16(s0 + so,            A + (size_t)(row0 + row) * K + kt + ch * 8);
            cp16(s0 + GT_BYTES + so, B + (size_t)(col0 + row) * K + kt + ch * 8);
        }
        CP_COMMIT();
    };

    load_stage(0, 0);
    for (int i = 0; i < nkt; i++) {
        const int b = i & 1;
        CP_WAIT0();
        __syncthreads();
        if (i + 1 < nkt) load_stage(i + 1, 1 - b);
        const uint32_t sA = sb + (uint32_t)b * GSTAGE;
        const uint32_t sB = sA + GT_BYTES;
        #pragma unroll
        for (int ks = 0; ks < 32; ks += 16) {
            uint32_t ah[4][4];
            #pragma unroll
            for (int mt = 0; mt < 4; mt++) {
                uint32_t ro = (uint32_t)((wm * 64 + mt * 16) * (GS_STRIDE * 2)) + (uint32_t)(ks * 2);
                ldsm_x4(ah[mt], sA + aoff + ro);
            }
            #pragma unroll
            for (int ntp = 0; ntp < 2; ntp++) {
                uint32_t b4[4];
                uint32_t ro = (uint32_t)((wn * 32 + ntp * 16) * (GS_STRIDE * 2)) + (uint32_t)(ks * 2);
                ldsm_x4(b4, sB + aoff + ro);
                #pragma unroll
                for (int hfn = 0; hfn < 2; hfn++) {
                    int nt = ntp * 2 + hfn;
                    uint32_t bh[2] = { b4[hfn], b4[hfn + 2] };
                    #pragma unroll
                    for (int mt = 0; mt < 4; mt++)
                        mma_f16(acc[mt][nt], ah[mt], bh);
                }
            }
        }
    }

    const int er = lane >> 2;
    const int ec = (lane & 3) * 2;
    #pragma unroll
    for (int mt = 0; mt < 4; mt++) {
        #pragma unroll
        for (int half = 0; half < 2; half++) {
            int row = row0 + wm * 64 + mt * 16 + er + half * 8;
            #pragma unroll
            for (int nt = 0; nt < 4; nt++) {
                int col = col0 + wn * 32 + nt * 8 + ec;
                float v0 = acc[mt][nt][half * 2 + 0] + bias[col];
                float v1 = acc[mt][nt][half * 2 + 1] + bias[col + 1];
                if (ACT == 1) {
                    v0 = 0.5f * v0 * (1.0f + erff(v0 * 0.70710678118654752f));
                    v1 = 0.5f * v1 * (1.0f + erff(v1 * 0.70710678118654752f));
                }
                if (RES) {
                    const float* rp = res + (size_t)row * N;
                    v0 += rp[col]; v1 += rp[col + 1];
                }
                if (OUTM == 0) {
                    float2 o; o.x = v0; o.y = v1;
                    *(float2*)(Cf + (size_t)row * N + col) = o;
                } else {
                    __half2 h2 = __floats2half2_rn(v0, v1);
                    *(__half2*)(Ch + (size_t)row * N + col) = h2;
                }
            }
        }
    }
}

// ---------------- batched weight prep ----------------
__global__ void __launch_bounds__(256)
wprep_kernel(const float* __restrict__ Wq,  const float* __restrict__ Wk,
             const float* __restrict__ Wv,  const float* __restrict__ Wo1,
             const float* __restrict__ Wo2,
             __half* __restrict__ wqkv, __half* __restrict__ w1,
             __half* __restrict__ w2)
{
    const float* in;
    __half* out;
    switch (blockIdx.z) {
        case 0: in = Wq;  out = wqkv;                        break;
        case 1: in = Wk;  out = wqkv + 1 * (size_t)DD * DD;  break;
        case 2: in = Wv;  out = wqkv + 2 * (size_t)DD * DD;  break;
        case 3: in = Wo1; out = w1;                          break;
        default: in = Wo2; out = w2;                         break;
    }
    __shared__ float t[32][33];
    int bx = blockIdx.x * 32, by = blockIdx.y * 32;
    int x = bx + threadIdx.x;
    #pragma unroll
    for (int j = 0; j < 32; j += 8)
        t[threadIdx.y + j][threadIdx.x] = in[(size_t)(by + threadIdx.y + j) * DD + x];
    __syncthreads();
    int x2 = by + threadIdx.x;
    #pragma unroll
    for (int j = 0; j < 32; j += 8)
        out[(size_t)(bx + threadIdx.y + j) * DD + x2] = __float2half(t[threadIdx.x][threadIdx.y + j]);
}

// ---------------- LayerNorm -> fp16 ----------------
__global__ void __launch_bounds__(256)
ln_half_kernel(const float* __restrict__ in, const float* __restrict__ gam,
               const float* __restrict__ bet, __half* __restrict__ oh)
{
    size_t base = (size_t)blockIdx.x * DD;
    int t4 = threadIdx.x * 4;
    float4 v = *(const float4*)&in[base + t4];
    float s  = v.x + v.y + v.z + v.w;
    float s2 = v.x*v.x + v.y*v.y + v.z*v.z + v.w*v.w;
    #pragma unroll
    for (int o = 16; o; o >>= 1) {
        s  += __shfl_xor_sync(0xffffffffu, s,  o);
        s2 += __shfl_xor_sync(0xffffffffu, s2, o);
    }
    __shared__ float rs[8], rs2[8];
    __shared__ float smu, srstd;
    int w = threadIdx.x >> 5, lane = threadIdx.x & 31;
    if (lane == 0) { rs[w] = s; rs2[w] = s2; }
    __syncthreads();
    if (threadIdx.x == 0) {
        float S = 0.f, S2 = 0.f;
        #pragma unroll
        for (int i = 0; i < 8; i++) { S += rs[i]; S2 += rs2[i]; }
        float mu  = S * (1.0f / DD);
        float var = S2 * (1.0f / DD) - mu * mu;
        smu = mu;
        srstd = rsqrtf(var + 1e-6f);
    }
    __syncthreads();
    float mu = smu, rstd = srstd;
    float4 g4 = *(const float4*)&gam[t4];
    float4 b4 = *(const float4*)&bet[t4];
    __half2 h0 = __floats2half2_rn((v.x - mu) * rstd * g4.x + b4.x,
                                   (v.y - mu) * rstd * g4.y + b4.y);
    __half2 h1 = __floats2half2_rn((v.z - mu) * rstd * g4.z + b4.z,
                                   (v.w - mu) * rstd * g4.w + b4.w);
    *(__half2*)(oh + base + t4)     = h0;
    *(__half2*)(oh + base + t4 + 2) = h1;
}

// ============ flash attention: fp16-acc MMAs + per-tile fp32 carry ============
#define ATSTRIDE 72
#define ATEN_BYTES (64*ATSTRIDE*2)   // 9216 per tensor
#define AOFF_K0 9216
#define AOFF_K1 18432
#define AOFF_V  27648
#define AOFF_M  36864
#define ATT2_SMEM (AOFF_M + 2*64*4)  // 37376

__global__ void __launch_bounds__(128, 4)
attn_mma_kernel(const __half* __restrict__ qkv,
                const int* __restrict__ mask,
                const float* __restrict__ x, float* __restrict__ res)
{
    extern __shared__ char sm8[];
    const uint32_t sb = smem_u32(sm8);
    __half* Qh = (__half*)sm8;
    float* maskadd = (float*)(sm8 + AOFF_M);

    const int tid  = threadIdx.x;
    const int wid  = tid >> 5;
    const int lane = tid & 31;
    const int b    = blockIdx.y >> 4;
    const int h    = blockIdx.y & 15;
    const int q0   = blockIdx.x * 64;
    const int er   = lane >> 2;
    const int qc   = lane & 3;

    auto load_k = [&](int kt, int buf) {
        uint32_t s0 = sb + (buf ? AOFF_K1 : AOFF_K0);
        #pragma unroll
        for (int u = 0; u < 4; u++) {
            int c = tid + u * 128;
            int row = c >> 3, ch = c & 7;
            size_t g = (size_t)(b * LL + kt + row) * D3 + DD + h * DHH + ch * 8;
            cp16(s0 + (uint32_t)(row * 144 + ch * 16), qkv + g);
        }
        CP_COMMIT();
    };
    auto load_v = [&](int kt) {
        uint32_t s0 = sb + AOFF_V;
        #pragma unroll
        for (int u = 0; u < 4; u++) {
            int c = tid + u * 128;
            int row = c >> 3, ch = c & 7;
            size_t g = (size_t)(b * LL + kt + row) * D3 + 2 * DD + h * DHH + ch * 8;
            cp16(s0 + (uint32_t)(row * 144 + ch * 16), qkv + g);
        }
        CP_COMMIT();
    };

    // ---- prologue ----
    {
        int lr = tid >> 1, lc = (tid & 1) * 32;
        size_t gq = (size_t)(b * LL + q0 + lr) * D3 + h * DHH + lc;
        #pragma unroll
        for (int j = 0; j < 4; j++)
            *(uint4*)&Qh[lr * ATSTRIDE + lc + 8*j] = *(const uint4*)(qkv + gq + 8*j);
    }
    load_k(0, 0);
    if (tid < 64)
        maskadd[tid] = (1.0f - (float)mask[b * LL + tid]) * (-1e30f);
    __syncthreads();

    // ---- persistent Q fragments ----
    const uint32_t aoff = (uint32_t)(((lane & 15) * ATSTRIDE + ((lane >> 4) & 1) * 8) * 2);
    uint32_t qh[4][4];
    #pragma unroll
    for (int s = 0; s < 4; s++) {
        uint32_t ro = (uint32_t)((wid * 16) * 144) + (uint32_t)(s * 32);
        ldsm_x4(qh[s], sb + aoff + ro);
    }

    const uint32_t voff = (uint32_t)(((lane & 7) + 8 * ((lane >> 3) & 1)) * 144 + ((lane >> 4) & 1) * 16);

    float m0 = -1e30f, m1 = -1e30f, l0 = 0.f, l1 = 0.f;
    float o[8][4];
    #pragma unroll
    for (int j = 0; j < 8; j++)
        #pragma unroll
        for (int t = 0; t < 4; t++) o[j][t] = 0.f;

    for (int it = 0; it < LL / 64; it++) {
        const int kt = it * 64;
        const int bb = it & 1;
        CP_WAIT0();
        __syncthreads();
        load_v(kt);

        const uint32_t sKh = sb + (bb ? AOFF_K1 : AOFF_K0);

        // ---- S = Q K^T (fp16 accum over K=64 only) ----
        uint32_t s16[8][2];
        #pragma unroll
        for (int j = 0; j < 8; j++) { s16[j][0] = 0u; s16[j][1] = 0u; }
        #pragma unroll
        for (int ks = 0; ks < 4; ks++) {
            #pragma unroll
            for (int jp = 0; jp < 4; jp++) {
                uint32_t k4[4];
                uint32_t ro = (uint32_t)((16 * jp) * 144) + (uint32_t)(ks * 32);
                ldsm_x4(k4, sKh + aoff + ro);
                #pragma unroll
                for (int hf = 0; hf < 2; hf++) {
                    uint32_t bh[2] = { k4[hf], k4[hf + 2] };
                    mma_f16h(s16[2*jp + hf], qh[ks], bh);
                }
            }
        }
        // unpack to fp32 for softmax
        float s[8][4];
        #pragma unroll
        for (int j = 0; j < 8; j++) {
            float2 fA = __half22float2(*(__half2*)&s16[j][0]);
            float2 fB = __half22float2(*(__half2*)&s16[j][1]);
            s[j][0] = fA.x; s[j][1] = fA.y;
            s[j][2] = fB.x; s[j][3] = fB.y;
        }

        // ---- online softmax (fp32, identical to R10) ----
        float mx0 = -1e30f, mx1 = -1e30f;
        #pragma unroll
        for (int j = 0; j < 8; j++) {
            float ma0 = maskadd[bb * 64 + 8 * j + 2 * qc];
            float ma1 = maskadd[bb * 64 + 8 * j + 2 * qc + 1];
            s[j][0] = s[j][0] * 0.125f + ma0;
            s[j][1] = s[j][1] * 0.125f + ma1;
            s[j][2] = s[j][2] * 0.125f + ma0;
            s[j][3] = s[j][3] * 0.125f + ma1;
            mx0 = fmaxf(mx0, fmaxf(s[j][0], s[j][1]));
            mx1 = fmaxf(mx1, fmaxf(s[j][2], s[j][3]));
        }
        mx0 = fmaxf(mx0, __shfl_xor_sync(0xffffffffu, mx0, 1));
        mx0 = fmaxf(mx0, __shfl_xor_sync(0xffffffffu, mx0, 2));
        mx1 = fmaxf(mx1, __shfl_xor_sync(0xffffffffu, mx1, 1));
        mx1 = fmaxf(mx1, __shfl_xor_sync(0xffffffffu, mx1, 2));
        float mn0 = fmaxf(m0, mx0), mn1 = fmaxf(m1, mx1);
        float c0 = __expf(m0 - mn0), c1 = __expf(m1 - mn1);
        m0 = mn0; m1 = mn1;
        float ls0 = 0.f, ls1 = 0.f;
        #pragma unroll
        for (int j = 0; j < 8; j++) {
            s[j][0] = __expf(s[j][0] - mn0);
            s[j][1] = __expf(s[j][1] - mn0);
            s[j][2] = __expf(s[j][2] - mn1);
            s[j][3] = __expf(s[j][3] - mn1);
            ls0 += s[j][0] + s[j][1];
            ls1 += s[j][2] + s[j][3];
        }
        l0 = l0 * c0 + ls0;
        l1 = l1 * c1 + ls1;

        CP_WAIT0();
        __syncthreads();
        if (it + 1 < LL / 64) {
            load_k(kt + 64, 1 - bb);
            if (tid < 64)
                maskadd[(1 - bb) * 64 + tid] =
                    (1.0f - (float)mask[b * LL + kt + 64 + tid]) * (-1e30f);
        }

        // ---- tile PV in fp16 accum (64 adds), then fp32 carry ----
        uint32_t pv16[8][2];
        #pragma unroll
        for (int j = 0; j < 8; j++) { pv16[j][0] = 0u; pv16[j][1] = 0u; }
        #pragma unroll
        for (int ks = 0; ks < 4; ks++) {
            uint32_t ph[4];
            __half2 p0 = __floats2half2_rn(s[2*ks][0],   s[2*ks][1]);
            __half2 p1 = __floats2half2_rn(s[2*ks][2],   s[2*ks][3]);
            __half2 p2 = __floats2half2_rn(s[2*ks+1][0], s[2*ks+1][1]);
            __half2 p3 = __floats2half2_rn(s[2*ks+1][2], s[2*ks+1][3]);
            ph[0] = *(uint32_t*)&p0; ph[1] = *(uint32_t*)&p1;
            ph[2] = *(uint32_t*)&p2; ph[3] = *(uint32_t*)&p3;
            uint32_t vbase = sb + AOFF_V + voff + (uint32_t)((16 * ks) * 144);
            #pragma unroll
            for (int jp = 0; jp < 4; jp++) {
                uint32_t v4[4];
                ldsm_x4_t(v4, vbase + (uint32_t)(32 * jp));
                mma_f16h(pv16[2*jp],     ph, &v4[0]);
                mma_f16h(pv16[2*jp + 1], ph, &v4[2]);
            }
        }
        // fp32 carry: o = o*c + tile
        #pragma unroll
        for (int j = 0; j < 8; j++) {
            float2 fA = __half22float2(*(__half2*)&pv16[j][0]);
            float2 fB = __half22float2(*(__half2*)&pv16[j][1]);
            o[j][0] = o[j][0] * c0 + fA.x;
            o[j][1] = o[j][1] * c0 + fA.y;
            o[j][2] = o[j][2] * c1 + fB.x;
            o[j][3] = o[j][3] * c1 + fB.y;
        }
    }

    // ---- finalize ----
    l0 += __shfl_xor_sync(0xffffffffu, l0, 1);
    l0 += __shfl_xor_sync(0xffffffffu, l0, 2);
    l1 += __shfl_xor_sync(0xffffffffu, l1, 1);
    l1 += __shfl_xor_sync(0xffffffffu, l1, 2);
    float i0 = 1.0f / l0, i1 = 1.0f / l1;

    const int row0 = q0 + wid * 16 + er;
    #pragma unroll
    for (int j = 0; j < 8; j++) {
        int col = h * DHH + 8 * j + 2 * qc;
        size_t base0 = (size_t)(b * LL + row0) * DD + col;
        size_t base1 = base0 + 8 * (size_t)DD;
        float2 r0, r1;
        r0.x = o[j][0] * i0 + x[base0];
        r0.y = o[j][1] * i0 + x[base0 + 1];
        r1.x = o[j][2] * i1 + x[base1];
        r1.y = o[j][3] * i1 + x[base1 + 1];
        *(float2*)&res[base0] = r0;
        *(float2*)&res[base1] = r1;
    }
}

// ---------------- launch ----------------
extern "C" void kernel_launch(void* const* d_in, const int* in_sizes, int n_in,
                              void* d_out, int out_size)
{
    const float* x    = (const float*)d_in[0];
    const int*   mask = (const int*)  d_in[1];
    const float* Wq   = (const float*)d_in[2];
    const float* bq   = (const float*)d_in[3];
    const float* Wk   = (const float*)d_in[4];
    const float* bk   = (const float*)d_in[5];
    const float* Wv   = (const float*)d_in[6];
    const float* bv   = (const float*)d_in[7];
    const float* g1   = (const float*)d_in[8];
    const float* b1   = (const float*)d_in[9];
    const float* g2   = (const float*)d_in[10];
    const float* b2   = (const float*)d_in[11];
    const float* Wo1  = (const float*)d_in[12];
    const float* bo1  = (const float*)d_in[13];
    const float* Wo2  = (const float*)d_in[14];
    const float* bo2  = (const float*)d_in[15];
    float* out = (float*)d_out;

    __half *h_, *qkv_, *ln2_, *mlp_, *wqkv_, *w1_, *w2_;
    float *res_, *bqkv;
    cudaGetSymbolAddress((void**)&h_,    g_h);
    cudaGetSymbolAddress((void**)&qkv_,  g_qkv);
    cudaGetSymbolAddress((void**)&ln2_,  g_ln2);
    cudaGetSymbolAddress((void**)&mlp_,  g_mlp);
    cudaGetSymbolAddress((void**)&wqkv_, g_wqkv);
    cudaGetSymbolAddress((void**)&w1_,   g_w1);
    cudaGetSymbolAddress((void**)&w2_,   g_w2);
    cudaGetSymbolAddress((void**)&res_,  g_res);
    cudaGetSymbolAddress((void**)&bqkv,  g_bqkv);

    cudaFuncSetAttribute(hgemm_kernel<0, false, 2>, cudaFuncAttributeMaxDynamicSharedMemorySize, HGEMM_SMEM);
    cudaFuncSetAttribute(hgemm_kernel<1, false, 2>, cudaFuncAttributeMaxDynamicSharedMemorySize, HGEMM_SMEM);
    cudaFuncSetAttribute(hgemm_kernel<0, true,  0>, cudaFuncAttributeMaxDynamicSharedMemorySize, HGEMM_SMEM);
    cudaFuncSetAttribute(attn_mma_kernel, cudaFuncAttributeMaxDynamicSharedMemorySize, ATT2_SMEM);

    // 0) weight prep + bias concat
    wprep_kernel<<<dim3(32, 32, 5), dim3(32, 8)>>>(Wq, Wk, Wv, Wo1, Wo2, wqkv_, w1_, w2_);
    cudaMemcpyAsync(bqkv,        bq, DD * sizeof(float), cudaMemcpyDeviceToDevice, 0);
    cudaMemcpyAsync(bqkv + DD,   bk, DD * sizeof(float), cudaMemcpyDeviceToDevice, 0);
    cudaMemcpyAsync(bqkv + 2*DD, bv, DD * sizeof(float), cudaMemcpyDeviceToDevice, 0);

    // 1) LN1 -> fp16
    ln_half_kernel<<<NTOK, 256>>>(x, g1, b1, h_);

    // 2) fused QKV projection (fp32 accum) -> packed qkv fp16
    hgemm_kernel<0, false, 2><<<dim3(D3 / 128, NTOK / 128), 256, HGEMM_SMEM>>>(
        h_, wqkv_, bqkv, nullptr, nullptr, qkv_, NTOK, D3, DD);

    // 3) flash attention (fp16-acc MMA + fp32 carry) + residual -> res (fp32)
    attn_mma_kernel<<<dim3(LL / 64, BB * HH), 128, ATT2_SMEM>>>(qkv_, mask, x, res_);

    // 4) LN2 -> fp16
    ln_half_kernel<<<NTOK, 256>>>(res_, g2, b2, ln2_);

    // 5) MLP up + GELU (fp32 accum) -> fp16
    hgemm_kernel<1, false, 2><<<dim3(DD / 128, NTOK / 128), 256, HGEMM_SMEM>>>(
        ln2_, w1_, bo1, nullptr, nullptr, mlp_, NTOK, DD, DD);

    // 6) MLP down + bias + residual (fp32 accum) -> out
    hgemm_kernel<0, true, 0><<<dim3(DD / 128, NTOK / 128), 256, HGEMM_SMEM>>>(
        mlp_, w2_, bo2, res_, out, nullptr, NTOK, DD, DD);
}

// round 13
// speedup vs baseline: 1.0575x; 1.0575x over previous
#include <cuda_runtime.h>
#include <cuda.h>
#include <cuda_fp16.h>
#include <math.h>
#include <stdint.h>

#define BB 4
#define LL 2048
#define DD 1024
#define HH 16
#define DHH 64
#define NTOK (BB*LL)   // 8192 rows
#define D3  (3*DD)     // 3072

// ---------------- scratch (device globals; no allocation allowed) ----------------
__device__ __align__(16) __half g_h   [NTOK*DD];
__device__ __align__(16) __half g_qkv [NTOK*D3];
__device__ __align__(16) __half g_ln2 [NTOK*DD];
__device__ __align__(16) __half g_mlp [NTOK*DD];
__device__ __align__(16) __half g_wqkv[3*DD*DD];
__device__ __align__(16) __half g_w1  [DD*DD];
__device__ __align__(16) __half g_w2  [DD*DD];
__device__ __align__(16) float  g_res [NTOK*DD];
__device__ __align__(16) float  g_bqkv[D3];

// ============================ helpers ============================
__device__ __forceinline__ uint32_t smem_u32(const void* p) {
    uint32_t a;
    asm("{ .reg .u64 t; cvta.to.shared.u64 t, %1; cvt.u32.u64 %0, t; }" : "=r"(a) : "l"(p));
    return a;
}
__device__ __forceinline__ void mma_f16(float* c, const uint32_t* a, const uint32_t* b) {
    asm volatile(
        "mma.sync.aligned.m16n8k16.row.col.f32.f16.f16.f32 "
        "{%0,%1,%2,%3}, {%4,%5,%6,%7}, {%8,%9}, {%0,%1,%2,%3};"
        : "+f"(c[0]), "+f"(c[1]), "+f"(c[2]), "+f"(c[3])
        : "r"(a[0]), "r"(a[1]), "r"(a[2]), "r"(a[3]), "r"(b[0]), "r"(b[1]));
}
__device__ __forceinline__ void ldsm_x4(uint32_t* r, uint32_t addr) {
    asm volatile("ldmatrix.sync.aligned.m8n8.x4.shared.b16 {%0,%1,%2,%3}, [%4];"
        : "=r"(r[0]), "=r"(r[1]), "=r"(r[2]), "=r"(r[3]) : "r"(addr));
}
__device__ __forceinline__ void ldsm_x4_t(uint32_t* r, uint32_t addr) {
    asm volatile("ldmatrix.sync.aligned.m8n8.x4.trans.shared.b16 {%0,%1,%2,%3}, [%4];"
        : "=r"(r[0]), "=r"(r[1]), "=r"(r[2]), "=r"(r[3]) : "r"(addr));
}
__device__ __forceinline__ void cp16(uint32_t dst, const void* src) {
    asm volatile("cp.async.cg.shared.global [%0], [%1], 16;" :: "r"(dst), "l"(src));
}
#define CP_COMMIT() asm volatile("cp.async.commit_group;" ::: "memory")
#define CP_WAIT0()  asm volatile("cp.async.wait_group 0;" ::: "memory")

// ============ fp16 GEMM, fp32 accum, BK=64 double-buffered ============
#define GS_STRIDE 72                      // halfs per smem row (144B)
#define GT_BYTES  (128*GS_STRIDE*2)       // 18432 per tensor
#define GSTAGE    (2*GT_BYTES)            // A + B = 36864
#define HGEMM_SMEM (2*GSTAGE)             // 73728

template<int ACT, bool RES, int OUTM>
__global__ void __launch_bounds__(256, 2)
hgemm_kernel(const __half* __restrict__ A, const __half* __restrict__ B,
             const float* __restrict__ bias, const float* __restrict__ res,
             float* __restrict__ Cf, __half* __restrict__ Ch,
             int M, int N, int K)
{
    extern __shared__ char dsm[];
    const uint32_t sb = smem_u32(dsm);

    const int tid  = threadIdx.x;
    const int wid  = tid >> 5;
    const int lane = tid & 31;
    const int wm   = wid >> 2;
    const int wn   = wid & 3;
    const int row0 = blockIdx.y * 128;
    const int col0 = blockIdx.x * 128;

    float acc[4][4][4];
    #pragma unroll
    for (int i = 0; i < 4; i++)
        #pragma unroll
        for (int j = 0; j < 4; j++)
            #pragma unroll
            for (int q = 0; q < 4; q++) acc[i][j][q] = 0.f;

    const uint32_t aoff = (uint32_t)(((lane & 15) * GS_STRIDE + ((lane >> 4) & 1) * 8) * 2);
    const int nkt = K / 64;

    // per stage: 128 rows x 8 chunks(16B) per tensor = 1024 cp / 256 thr = 4 each
    auto load_stage = [&](int i, int buf) {
        uint32_t s0 = sb + (uint32_t)buf * GSTAGE;
        int kt = i * 64;
        #pragma unroll
        for (int u = 0; u < 4; u++) {
            int c   = tid + u * 256;
            int row = c >> 3;
            int ch  = c & 7;
            uint32_t so = (uint32_t)(row * (GS_STRIDE * 2) + ch * 16);
            cp16(s0 + so,            A + (size_t)(row0 + row) * K + kt + ch * 8);
            cp16(s0 + GT_BYTES + so, B + (size_t)(col0 + row) * K + kt + ch * 8);
        }
        CP_COMMIT();
    };

    load_stage(0, 0);
    for (int i = 0; i < nkt; i++) {
        const int b = i & 1;
        CP_WAIT0();
        __syncthreads();
        if (i + 1 < nkt) load_stage(i + 1, 1 - b);
        const uint32_t sA = sb + (uint32_t)b * GSTAGE;
        const uint32_t sB = sA + GT_BYTES;
        #pragma unroll
        for (int ks = 0; ks < 64; ks += 16) {
            uint32_t ah[4][4];
            #pragma unroll
            for (int mt = 0; mt < 4; mt++) {
                uint32_t ro = (uint32_t)((wm * 64 + mt * 16) * (GS_STRIDE * 2)) + (uint32_t)(ks * 2);
                ldsm_x4(ah[mt], sA + aoff + ro);
            }
            #pragma unroll
            for (int ntp = 0; ntp < 2; ntp++) {
                uint32_t b4[4];
                uint32_t ro = (uint32_t)((wn * 32 + ntp * 16) * (GS_STRIDE * 2)) + (uint32_t)(ks * 2);
                ldsm_x4(b4, sB + aoff + ro);
                #pragma unroll
                for (int hfn = 0; hfn < 2; hfn++) {
                    int nt = ntp * 2 + hfn;
                    uint32_t bh[2] = { b4[hfn], b4[hfn + 2] };
                    #pragma unroll
                    for (int mt = 0; mt < 4; mt++)
                        mma_f16(acc[mt][nt], ah[mt], bh);
                }
            }
        }
    }

    const int er = lane >> 2;
    const int ec = (lane & 3) * 2;
    #pragma unroll
    for (int mt = 0; mt < 4; mt++) {
        #pragma unroll
        for (int half = 0; half < 2; half++) {
            int row = row0 + wm * 64 + mt * 16 + er + half * 8;
            #pragma unroll
            for (int nt = 0; nt < 4; nt++) {
                int col = col0 + wn * 32 + nt * 8 + ec;
                float v0 = acc[mt][nt][half * 2 + 0] + bias[col];
                float v1 = acc[mt][nt][half * 2 + 1] + bias[col + 1];
                if (ACT == 1) {
                    v0 = 0.5f * v0 * (1.0f + erff(v0 * 0.70710678118654752f));
                    v1 = 0.5f * v1 * (1.0f + erff(v1 * 0.70710678118654752f));
                }
                if (RES) {
                    const float* rp = res + (size_t)row * N;
                    v0 += rp[col]; v1 += rp[col + 1];
                }
                if (OUTM == 0) {
                    float2 o; o.x = v0; o.y = v1;
                    *(float2*)(Cf + (size_t)row * N + col) = o;
                } else {
                    __half2 h2 = __floats2half2_rn(v0, v1);
                    *(__half2*)(Ch + (size_t)row * N + col) = h2;
                }
            }
        }
    }
}

// ---------------- batched weight prep ----------------
__global__ void __launch_bounds__(256)
wprep_kernel(const float* __restrict__ Wq,  const float* __restrict__ Wk,
             const float* __restrict__ Wv,  const float* __restrict__ Wo1,
             const float* __restrict__ Wo2,
             __half* __restrict__ wqkv, __half* __restrict__ w1,
             __half* __restrict__ w2)
{
    const float* in;
    __half* out;
    switch (blockIdx.z) {
        case 0: in = Wq;  out = wqkv;                        break;
        case 1: in = Wk;  out = wqkv + 1 * (size_t)DD * DD;  break;
        case 2: in = Wv;  out = wqkv + 2 * (size_t)DD * DD;  break;
        case 3: in = Wo1; out = w1;                          break;
        default: in = Wo2; out = w2;                         break;
    }
    __shared__ float t[32][33];
    int bx = blockIdx.x * 32, by = blockIdx.y * 32;
    int x = bx + threadIdx.x;
    #pragma unroll
    for (int j = 0; j < 32; j += 8)
        t[threadIdx.y + j][threadIdx.x] = in[(size_t)(by + threadIdx.y + j) * DD + x];
    __syncthreads();
    int x2 = by + threadIdx.x;
    #pragma unroll
    for (int j = 0; j < 32; j += 8)
        out[(size_t)(bx + threadIdx.y + j) * DD + x2] = __float2half(t[threadIdx.x][threadIdx.y + j]);
}

// ---------------- LayerNorm -> fp16 ----------------
__global__ void __launch_bounds__(256)
ln_half_kernel(const float* __restrict__ in, const float* __restrict__ gam,
               const float* __restrict__ bet, __half* __restrict__ oh)
{
    size_t base = (size_t)blockIdx.x * DD;
    int t4 = threadIdx.x * 4;
    float4 v = *(const float4*)&in[base + t4];
    float s  = v.x + v.y + v.z + v.w;
    float s2 = v.x*v.x + v.y*v.y + v.z*v.z + v.w*v.w;
    #pragma unroll
    for (int o = 16; o; o >>= 1) {
        s  += __shfl_xor_sync(0xffffffffu, s,  o);
        s2 += __shfl_xor_sync(0xffffffffu, s2, o);
    }
    __shared__ float rs[8], rs2[8];
    __shared__ float smu, srstd;
    int w = threadIdx.x >> 5, lane = threadIdx.x & 31;
    if (lane == 0) { rs[w] = s; rs2[w] = s2; }
    __syncthreads();
    if (threadIdx.x == 0) {
        float S = 0.f, S2 = 0.f;
        #pragma unroll
        for (int i = 0; i < 8; i++) { S += rs[i]; S2 += rs2[i]; }
        float mu  = S * (1.0f / DD);
        float var = S2 * (1.0f / DD) - mu * mu;
        smu = mu;
        srstd = rsqrtf(var + 1e-6f);
    }
    __syncthreads();
    float mu = smu, rstd = srstd;
    float4 g4 = *(const float4*)&gam[t4];
    float4 b4 = *(const float4*)&bet[t4];
    __half2 h0 = __floats2half2_rn((v.x - mu) * rstd * g4.x + b4.x,
                                   (v.y - mu) * rstd * g4.y + b4.y);
    __half2 h1 = __floats2half2_rn((v.z - mu) * rstd * g4.z + b4.z,
                                   (v.w - mu) * rstd * g4.w + b4.w);
    *(__half2*)(oh + base + t4)     = h0;
    *(__half2*)(oh + base + t4 + 2) = h1;
}

// ============ fp16 flash attention, K+V double-buffered, 1 sync/tile ============
#define ATSTRIDE 72
#define ATEN_BYTES (64*ATSTRIDE*2)   // 9216 per tensor
#define AOFF_K0 9216
#define AOFF_K1 18432
#define AOFF_V0 27648
#define AOFF_V1 36864
#define AOFF_M  46080
#define ATT2_SMEM (AOFF_M + 2*64*4)  // 46592

__global__ void __launch_bounds__(128, 4)
attn_mma_kernel(const __half* __restrict__ qkv,
                const int* __restrict__ mask,
                const float* __restrict__ x, float* __restrict__ res)
{
    extern __shared__ char sm8[];
    const uint32_t sb = smem_u32(sm8);
    __half* Qh = (__half*)sm8;
    float* maskadd = (float*)(sm8 + AOFF_M);

    const int tid  = threadIdx.x;
    const int wid  = tid >> 5;
    const int lane = tid & 31;
    const int b    = blockIdx.y >> 4;
    const int h    = blockIdx.y & 15;
    const int q0   = blockIdx.x * 64;
    const int er   = lane >> 2;
    const int qc   = lane & 3;

    // one combined K+V load per tile (single commit group)
    auto load_kv = [&](int kt, int buf) {
        uint32_t sk = sb + (buf ? AOFF_K1 : AOFF_K0);
        uint32_t sv = sb + (buf ? AOFF_V1 : AOFF_V0);
        #pragma unroll
        for (int u = 0; u < 4; u++) {
            int c = tid + u * 128;
            int row = c >> 3, ch = c & 7;
            size_t gbase = (size_t)(b * LL + kt + row) * D3 + h * DHH + ch * 8;
            uint32_t so = (uint32_t)(row * 144 + ch * 16);
            cp16(sk + so, qkv + gbase + DD);
            cp16(sv + so, qkv + gbase + 2 * DD);
        }
        CP_COMMIT();
    };

    // ---- prologue ----
    {
        int lr = tid >> 1, lc = (tid & 1) * 32;
        size_t gq = (size_t)(b * LL + q0 + lr) * D3 + h * DHH + lc;
        #pragma unroll
        for (int j = 0; j < 4; j++)
            *(uint4*)&Qh[lr * ATSTRIDE + lc + 8*j] = *(const uint4*)(qkv + gq + 8*j);
    }
    load_kv(0, 0);
    if (tid < 64)
        maskadd[tid] = (1.0f - (float)mask[b * LL + tid]) * (-1e30f);
    __syncthreads();

    // ---- persistent Q fragments ----
    const uint32_t aoff = (uint32_t)(((lane & 15) * ATSTRIDE + ((lane >> 4) & 1) * 8) * 2);
    uint32_t qh[4][4];
    #pragma unroll
    for (int s = 0; s < 4; s++) {
        uint32_t ro = (uint32_t)((wid * 16) * 144) + (uint32_t)(s * 32);
        ldsm_x4(qh[s], sb + aoff + ro);
    }

    const uint32_t voff = (uint32_t)(((lane & 7) + 8 * ((lane >> 3) & 1)) * 144 + ((lane >> 4) & 1) * 16);

    float m0 = -1e30f, m1 = -1e30f, l0 = 0.f, l1 = 0.f;
    float o[8][4];
    #pragma unroll
    for (int j = 0; j < 8; j++)
        #pragma unroll
        for (int t = 0; t < 4; t++) o[j][t] = 0.f;

    for (int it = 0; it < LL / 64; it++) {
        const int kt = it * 64;
        const int bb = it & 1;
        CP_WAIT0();            // K(it)+V(it) ready
        __syncthreads();       // publishes mask(it) too
        if (it + 1 < LL / 64) {
            load_kv(kt + 64, 1 - bb);   // overlaps ALL of this tile's compute
            if (tid < 64)
                maskadd[(1 - bb) * 64 + tid] =
                    (1.0f - (float)mask[b * LL + kt + 64 + tid]) * (-1e30f);
        }

        const uint32_t sKh = sb + (bb ? AOFF_K1 : AOFF_K0);
        const uint32_t sVh = sb + (bb ? AOFF_V1 : AOFF_V0);

        // ---- S = Q K^T (fp32 accum) ----
        float s[8][4];
        #pragma unroll
        for (int j = 0; j < 8; j++)
            #pragma unroll
            for (int t = 0; t < 4; t++) s[j][t] = 0.f;
        #pragma unroll
        for (int ks = 0; ks < 4; ks++) {
            #pragma unroll
            for (int jp = 0; jp < 4; jp++) {
                uint32_t k4[4];
                uint32_t ro = (uint32_t)((16 * jp) * 144) + (uint32_t)(ks * 32);
                ldsm_x4(k4, sKh + aoff + ro);
                #pragma unroll
                for (int hf = 0; hf < 2; hf++) {
                    uint32_t bh[2] = { k4[hf], k4[hf + 2] };
                    mma_f16(s[2*jp + hf], qh[ks], bh);
                }
            }
        }

        // ---- online softmax (fp32) ----
        float mx0 = -1e30f, mx1 = -1e30f;
        #pragma unroll
        for (int j = 0; j < 8; j++) {
            float ma0 = maskadd[bb * 64 + 8 * j + 2 * qc];
            float ma1 = maskadd[bb * 64 + 8 * j + 2 * qc + 1];
            s[j][0] = s[j][0] * 0.125f + ma0;
            s[j][1] = s[j][1] * 0.125f + ma1;
            s[j][2] = s[j][2] * 0.125f + ma0;
            s[j][3] = s[j][3] * 0.125f + ma1;
            mx0 = fmaxf(mx0, fmaxf(s[j][0], s[j][1]));
            mx1 = fmaxf(mx1, fmaxf(s[j][2], s[j][3]));
        }
        mx0 = fmaxf(mx0, __shfl_xor_sync(0xffffffffu, mx0, 1));
        mx0 = fmaxf(mx0, __shfl_xor_sync(0xffffffffu, mx0, 2));
        mx1 = fmaxf(mx1, __shfl_xor_sync(0xffffffffu, mx1, 1));
        mx1 = fmaxf(mx1, __shfl_xor_sync(0xffffffffu, mx1, 2));
        float mn0 = fmaxf(m0, mx0), mn1 = fmaxf(m1, mx1);
        float c0 = __expf(m0 - mn0), c1 = __expf(m1 - mn1);
        m0 = mn0; m1 = mn1;
        float ls0 = 0.f, ls1 = 0.f;
        #pragma unroll
        for (int j = 0; j < 8; j++) {
            s[j][0] = __expf(s[j][0] - mn0);
            s[j][1] = __expf(s[j][1] - mn0);
            s[j][2] = __expf(s[j][2] - mn1);
            s[j][3] = __expf(s[j][3] - mn1);
            ls0 += s[j][0] + s[j][1];
            ls1 += s[j][2] + s[j][3];
        }
        l0 = l0 * c0 + ls0;
        l1 = l1 * c1 + ls1;
        #pragma unroll
        for (int j = 0; j < 8; j++) {
            o[j][0] *= c0; o[j][1] *= c0;
            o[j][2] *= c1; o[j][3] *= c1;
        }

        // ---- O += P @ V (fp32 accum) ----
        #pragma unroll
        for (int ks = 0; ks < 4; ks++) {
            uint32_t ph[4];
            __half2 p0 = __floats2half2_rn(s[2*ks][0],   s[2*ks][1]);
            __half2 p1 = __floats2half2_rn(s[2*ks][2],   s[2*ks][3]);
            __half2 p2 = __floats2half2_rn(s[2*ks+1][0], s[2*ks+1][1]);
            __half2 p3 = __floats2half2_rn(s[2*ks+1][2], s[2*ks+1][3]);
            ph[0] = *(uint32_t*)&p0; ph[1] = *(uint32_t*)&p1;
            ph[2] = *(uint32_t*)&p2; ph[3] = *(uint32_t*)&p3;
            uint32_t vbase = sVh + voff + (uint32_t)((16 * ks) * 144);
            #pragma unroll
            for (int jp = 0; jp < 4; jp++) {
                uint32_t v4[4];
                ldsm_x4_t(v4, vbase + (uint32_t)(32 * jp));
                mma_f16(o[2*jp],     ph, &v4[0]);
                mma_f16(o[2*jp + 1], ph, &v4[2]);
            }
        }
    }

    // ---- finalize ----
    l0 += __shfl_xor_sync(0xffffffffu, l0, 1);
    l0 += __shfl_xor_sync(0xffffffffu, l0, 2);
    l1 += __shfl_xor_sync(0xffffffffu, l1, 1);
    l1 += __shfl_xor_sync(0xffffffffu, l1, 2);
    float i0 = 1.0f / l0, i1 = 1.0f / l1;

    const int row0 = q0 + wid * 16 + er;
    #pragma unroll
    for (int j = 0; j < 8; j++) {
        int col = h * DHH + 8 * j + 2 * qc;
        size_t base0 = (size_t)(b * LL + row0) * DD + col;
        size_t base1 = base0 + 8 * (size_t)DD;
        float2 r0, r1;
        r0.x = o[j][0] * i0 + x[base0];
        r0.y = o[j][1] * i0 + x[base0 + 1];
        r1.x = o[j][2] * i1 + x[base1];
        r1.y = o[j][3] * i1 + x[base1 + 1];
        *(float2*)&res[base0] = r0;
        *(float2*)&res[base1] = r1;
    }
}

// ---------------- launch ----------------
extern "C" void kernel_launch(void* const* d_in, const int* in_sizes, int n_in,
                              void* d_out, int out_size)
{
    const float* x    = (const float*)d_in[0];
    const int*   mask = (const int*)  d_in[1];
    const float* Wq   = (const float*)d_in[2];
    const float* bq   = (const float*)d_in[3];
    const float* Wk   = (const float*)d_in[4];
    const float* bk   = (const float*)d_in[5];
    const float* Wv   = (const float*)d_in[6];
    const float* bv   = (const float*)d_in[7];
    const float* g1   = (const float*)d_in[8];
    const float* b1   = (const float*)d_in[9];
    const float* g2   = (const float*)d_in[10];
    const float* b2   = (const float*)d_in[11];
    const float* Wo1  = (const float*)d_in[12];
    const float* bo1  = (const float*)d_in[13];
    const float* Wo2  = (const float*)d_in[14];
    const float* bo2  = (const float*)d_in[15];
    float* out = (float*)d_out;

    __half *h_, *qkv_, *ln2_, *mlp_, *wqkv_, *w1_, *w2_;
    float *res_, *bqkv;
    cudaGetSymbolAddress((void**)&h_,    g_h);
    cudaGetSymbolAddress((void**)&qkv_,  g_qkv);
    cudaGetSymbolAddress((void**)&ln2_,  g_ln2);
    cudaGetSymbolAddress((void**)&mlp_,  g_mlp);
    cudaGetSymbolAddress((void**)&wqkv_, g_wqkv);
    cudaGetSymbolAddress((void**)&w1_,   g_w1);
    cudaGetSymbolAddress((void**)&w2_,   g_w2);
    cudaGetSymbolAddress((void**)&res_,  g_res);
    cudaGetSymbolAddress((void**)&bqkv,  g_bqkv);

    cudaFuncSetAttribute(hgemm_kernel<0, false, 2>, cudaFuncAttributeMaxDynamicSharedMemorySize, HGEMM_SMEM);
    cudaFuncSetAttribute(hgemm_kernel<1, false, 2>, cudaFuncAttributeMaxDynamicSharedMemorySize, HGEMM_SMEM);
    cudaFuncSetAttribute(hgemm_kernel<0, true,  0>, cudaFuncAttributeMaxDynamicSharedMemorySize, HGEMM_SMEM);
    cudaFuncSetAttribute(attn_mma_kernel, cudaFuncAttributeMaxDynamicSharedMemorySize, ATT2_SMEM);

    // 0) weight prep + bias concat
    wprep_kernel<<<dim3(32, 32, 5), dim3(32, 8)>>>(Wq, Wk, Wv, Wo1, Wo2, wqkv_, w1_, w2_);
    cudaMemcpyAsync(bqkv,        bq, DD * sizeof(float), cudaMemcpyDeviceToDevice, 0);
    cudaMemcpyAsync(bqkv + DD,   bk, DD * sizeof(float), cudaMemcpyDeviceToDevice, 0);
    cudaMemcpyAsync(bqkv + 2*DD, bv, DD * sizeof(float), cudaMemcpyDeviceToDevice, 0);

    // 1) LN1 -> fp16
    ln_half_kernel<<<NTOK, 256>>>(x, g1, b1, h_);

    // 2) fused QKV projection -> packed qkv fp16
    hgemm_kernel<0, false, 2><<<dim3(D3 / 128, NTOK / 128), 256, HGEMM_SMEM>>>(
        h_, wqkv_, bqkv, nullptr, nullptr, qkv_, NTOK, D3, DD);

    // 3) flash attention + residual -> res (fp32)
    attn_mma_kernel<<<dim3(LL / 64, BB * HH), 128, ATT2_SMEM>>>(qkv_, mask, x, res_);

    // 4) LN2 -> fp16
    ln_half_kernel<<<NTOK, 256>>>(res_, g2, b2, ln2_);

    // 5) MLP up + GELU -> fp16
    hgemm_kernel<1, false, 2><<<dim3(DD / 128, NTOK / 128), 256, HGEMM_SMEM>>>(
        ln2_, w1_, bo1, nullptr, nullptr, mlp_, NTOK, DD, DD);

    // 6) MLP down + bias + residual -> out (fp32)
    hgemm_kernel<0, true, 0><<<dim3(DD / 128, NTOK / 128), 256, HGEMM_SMEM>>>(
        mlp_, w2_, bo2, res_, out, nullptr, NTOK, DD, DD);
}

// round 14
// speedup vs baseline: 1.0898x; 1.0305x over previous
#include <cuda_runtime.h>
#include <cuda.h>
#include <cuda_fp16.h>
#include <math.h>
#include <stdint.h>

#define BB 4
#define LL 2048
#define DD 1024
#define HH 16
#define DHH 64
#define NTOK (BB*LL)   // 8192 rows
#define D3  (3*DD)     // 3072

// ---------------- scratch (device globals; no allocation allowed) ----------------
__device__ __align__(16) __half g_h   [NTOK*DD];
__device__ __align__(16) __half g_qkv [NTOK*D3];
__device__ __align__(16) __half g_ln2 [NTOK*DD];
__device__ __align__(16) __half g_mlp [NTOK*DD];
__device__ __align__(16) __half g_wqkv[3*DD*DD];
__device__ __align__(16) __half g_w1  [DD*DD];
__device__ __align__(16) __half g_w2  [DD*DD];
__device__ __align__(16) float  g_res [NTOK*DD];
__device__ __align__(16) float  g_bqkv[D3];

// ============================ helpers ============================
__device__ __forceinline__ uint32_t smem_u32(const void* p) {
    uint32_t a;
    asm("{ .reg .u64 t; cvta.to.shared.u64 t, %1; cvt.u32.u64 %0, t; }" : "=r"(a) : "l"(p));
    return a;
}
__device__ __forceinline__ void mma_f16(float* c, const uint32_t* a, const uint32_t* b) {
    asm volatile(
        "mma.sync.aligned.m16n8k16.row.col.f32.f16.f16.f32 "
        "{%0,%1,%2,%3}, {%4,%5,%6,%7}, {%8,%9}, {%0,%1,%2,%3};"
        : "+f"(c[0]), "+f"(c[1]), "+f"(c[2]), "+f"(c[3])
        : "r"(a[0]), "r"(a[1]), "r"(a[2]), "r"(a[3]), "r"(b[0]), "r"(b[1]));
}
__device__ __forceinline__ void ldsm_x4(uint32_t* r, uint32_t addr) {
    asm volatile("ldmatrix.sync.aligned.m8n8.x4.shared.b16 {%0,%1,%2,%3}, [%4];"
        : "=r"(r[0]), "=r"(r[1]), "=r"(r[2]), "=r"(r[3]) : "r"(addr));
}
__device__ __forceinline__ void ldsm_x4_t(uint32_t* r, uint32_t addr) {
    asm volatile("ldmatrix.sync.aligned.m8n8.x4.trans.shared.b16 {%0,%1,%2,%3}, [%4];"
        : "=r"(r[0]), "=r"(r[1]), "=r"(r[2]), "=r"(r[3]) : "r"(addr));
}
__device__ __forceinline__ void cp16(uint32_t dst, const void* src) {
    asm volatile("cp.async.cg.shared.global [%0], [%1], 16;" :: "r"(dst), "l"(src));
}
#define CP_COMMIT() asm volatile("cp.async.commit_group;" ::: "memory")
#define CP_WAIT0()  asm volatile("cp.async.wait_group 0;" ::: "memory")

// ============ fp16 GEMM, fp32 accum, BK=64 double-buffered (R13 best) ============
#define GS_STRIDE 72                      // halfs per smem row (144B)
#define GT_BYTES  (128*GS_STRIDE*2)       // 18432 per tensor
#define GSTAGE    (2*GT_BYTES)            // A + B = 36864
#define HGEMM_SMEM (2*GSTAGE)             // 73728

template<int ACT, bool RES, int OUTM>
__global__ void __launch_bounds__(256, 2)
hgemm_kernel(const __half* __restrict__ A, const __half* __restrict__ B,
             const float* __restrict__ bias, const float* __restrict__ res,
             float* __restrict__ Cf, __half* __restrict__ Ch,
             int M, int N, int K)
{
    extern __shared__ char dsm[];
    const uint32_t sb = smem_u32(dsm);

    const int tid  = threadIdx.x;
    const int wid  = tid >> 5;
    const int lane = tid & 31;
    const int wm   = wid >> 2;
    const int wn   = wid & 3;
    const int row0 = blockIdx.y * 128;
    const int col0 = blockIdx.x * 128;

    float acc[4][4][4];
    #pragma unroll
    for (int i = 0; i < 4; i++)
        #pragma unroll
        for (int j = 0; j < 4; j++)
            #pragma unroll
            for (int q = 0; q < 4; q++) acc[i][j][q] = 0.f;

    const uint32_t aoff = (uint32_t)(((lane & 15) * GS_STRIDE + ((lane >> 4) & 1) * 8) * 2);
    const int nkt = K / 64;

    auto load_stage = [&](int i, int buf) {
        uint32_t s0 = sb + (uint32_t)buf * GSTAGE;
        int kt = i * 64;
        #pragma unroll
        for (int u = 0; u < 4; u++) {
            int c   = tid + u * 256;
            int row = c >> 3;
            int ch  = c & 7;
            uint32_t so = (uint32_t)(row * (GS_STRIDE * 2) + ch * 16);
            cp16(s0 + so,            A + (size_t)(row0 + row) * K + kt + ch * 8);
            cp16(s0 + GT_BYTES + so, B + (size_t)(col0 + row) * K + kt + ch * 8);
        }
        CP_COMMIT();
    };

    load_stage(0, 0);
    for (int i = 0; i < nkt; i++) {
        const int b = i & 1;
        CP_WAIT0();
        __syncthreads();
        if (i + 1 < nkt) load_stage(i + 1, 1 - b);
        const uint32_t sA = sb + (uint32_t)b * GSTAGE;
        const uint32_t sB = sA + GT_BYTES;
        #pragma unroll
        for (int ks = 0; ks < 64; ks += 16) {
            uint32_t ah[4][4];
            #pragma unroll
            for (int mt = 0; mt < 4; mt++) {
                uint32_t ro = (uint32_t)((wm * 64 + mt * 16) * (GS_STRIDE * 2)) + (uint32_t)(ks * 2);
                ldsm_x4(ah[mt], sA + aoff + ro);
            }
            #pragma unroll
            for (int ntp = 0; ntp < 2; ntp++) {
                uint32_t b4[4];
                uint32_t ro = (uint32_t)((wn * 32 + ntp * 16) * (GS_STRIDE * 2)) + (uint32_t)(ks * 2);
                ldsm_x4(b4, sB + aoff + ro);
                #pragma unroll
                for (int hfn = 0; hfn < 2; hfn++) {
                    int nt = ntp * 2 + hfn;
                    uint32_t bh[2] = { b4[hfn], b4[hfn + 2] };
                    #pragma unroll
                    for (int mt = 0; mt < 4; mt++)
                        mma_f16(acc[mt][nt], ah[mt], bh);
                }
            }
        }
    }

    const int er = lane >> 2;
    const int ec = (lane & 3) * 2;
    #pragma unroll
    for (int mt = 0; mt < 4; mt++) {
        #pragma unroll
        for (int half = 0; half < 2; half++) {
            int row = row0 + wm * 64 + mt * 16 + er + half * 8;
            #pragma unroll
            for (int nt = 0; nt < 4; nt++) {
                int col = col0 + wn * 32 + nt * 8 + ec;
                float v0 = acc[mt][nt][half * 2 + 0] + bias[col];
                float v1 = acc[mt][nt][half * 2 + 1] + bias[col + 1];
                if (ACT == 1) {
                    v0 = 0.5f * v0 * (1.0f + erff(v0 * 0.70710678118654752f));
                    v1 = 0.5f * v1 * (1.0f + erff(v1 * 0.70710678118654752f));
                }
                if (RES) {
                    const float* rp = res + (size_t)row * N;
                    v0 += rp[col]; v1 += rp[col + 1];
                }
                if (OUTM == 0) {
                    float2 o; o.x = v0; o.y = v1;
                    *(float2*)(Cf + (size_t)row * N + col) = o;
                } else {
                    __half2 h2 = __floats2half2_rn(v0, v1);
                    *(__half2*)(Ch + (size_t)row * N + col) = h2;
                }
            }
        }
    }
}

// ---------------- batched weight prep ----------------
__global__ void __launch_bounds__(256)
wprep_kernel(const float* __restrict__ Wq,  const float* __restrict__ Wk,
             const float* __restrict__ Wv,  const float* __restrict__ Wo1,
             const float* __restrict__ Wo2,
             __half* __restrict__ wqkv, __half* __restrict__ w1,
             __half* __restrict__ w2)
{
    const float* in;
    __half* out;
    switch (blockIdx.z) {
        case 0: in = Wq;  out = wqkv;                        break;
        case 1: in = Wk;  out = wqkv + 1 * (size_t)DD * DD;  break;
        case 2: in = Wv;  out = wqkv + 2 * (size_t)DD * DD;  break;
        case 3: in = Wo1; out = w1;                          break;
        default: in = Wo2; out = w2;                         break;
    }
    __shared__ float t[32][33];
    int bx = blockIdx.x * 32, by = blockIdx.y * 32;
    int x = bx + threadIdx.x;
    #pragma unroll
    for (int j = 0; j < 32; j += 8)
        t[threadIdx.y + j][threadIdx.x] = in[(size_t)(by + threadIdx.y + j) * DD + x];
    __syncthreads();
    int x2 = by + threadIdx.x;
    #pragma unroll
    for (int j = 0; j < 32; j += 8)
        out[(size_t)(bx + threadIdx.y + j) * DD + x2] = __float2half(t[threadIdx.x][threadIdx.y + j]);
}

// ---------------- LayerNorm -> fp16 ----------------
__global__ void __launch_bounds__(256)
ln_half_kernel(const float* __restrict__ in, const float* __restrict__ gam,
               const float* __restrict__ bet, __half* __restrict__ oh)
{
    size_t base = (size_t)blockIdx.x * DD;
    int t4 = threadIdx.x * 4;
    float4 v = *(const float4*)&in[base + t4];
    float s  = v.x + v.y + v.z + v.w;
    float s2 = v.x*v.x + v.y*v.y + v.z*v.z + v.w*v.w;
    #pragma unroll
    for (int o = 16; o; o >>= 1) {
        s  += __shfl_xor_sync(0xffffffffu, s,  o);
        s2 += __shfl_xor_sync(0xffffffffu, s2, o);
    }
    __shared__ float rs[8], rs2[8];
    __shared__ float smu, srstd;
    int w = threadIdx.x >> 5, lane = threadIdx.x & 31;
    if (lane == 0) { rs[w] = s; rs2[w] = s2; }
    __syncthreads();
    if (threadIdx.x == 0) {
        float S = 0.f, S2 = 0.f;
        #pragma unroll
        for (int i = 0; i < 8; i++) { S += rs[i]; S2 += rs2[i]; }
        float mu  = S * (1.0f / DD);
        float var = S2 * (1.0f / DD) - mu * mu;
        smu = mu;
        srstd = rsqrtf(var + 1e-6f);
    }
    __syncthreads();
    float mu = smu, rstd = srstd;
    float4 g4 = *(const float4*)&gam[t4];
    float4 b4 = *(const float4*)&bet[t4];
    __half2 h0 = __floats2half2_rn((v.x - mu) * rstd * g4.x + b4.x,
                                   (v.y - mu) * rstd * g4.y + b4.y);
    __half2 h1 = __floats2half2_rn((v.z - mu) * rstd * g4.z + b4.z,
                                   (v.w - mu) * rstd * g4.w + b4.w);
    *(__half2*)(oh + base + t4)     = h0;
    *(__half2*)(oh + base + t4 + 2) = h1;
}

// ============ fp16 flash attention (R10 structure: K dbl-buf, V single) ============
#define ATSTRIDE 72
#define ATEN_BYTES (64*ATSTRIDE*2)   // 9216 per tensor
#define AOFF_K0 9216
#define AOFF_K1 18432
#define AOFF_V  27648
#define AOFF_M  36864
#define ATT2_SMEM (AOFF_M + 2*64*4)  // 37376

__global__ void __launch_bounds__(128, 4)
attn_mma_kernel(const __half* __restrict__ qkv,
                const int* __restrict__ mask,
                const float* __restrict__ x, float* __restrict__ res)
{
    extern __shared__ char sm8[];
    const uint32_t sb = smem_u32(sm8);
    __half* Qh = (__half*)sm8;
    float* maskadd = (float*)(sm8 + AOFF_M);

    const int tid  = threadIdx.x;
    const int wid  = tid >> 5;
    const int lane = tid & 31;
    const int b    = blockIdx.y >> 4;
    const int h    = blockIdx.y & 15;
    const int q0   = blockIdx.x * 64;
    const int er   = lane >> 2;
    const int qc   = lane & 3;

    auto load_k = [&](int kt, int buf) {
        uint32_t s0 = sb + (buf ? AOFF_K1 : AOFF_K0);
        #pragma unroll
        for (int u = 0; u < 4; u++) {
            int c = tid + u * 128;
            int row = c >> 3, ch = c & 7;
            size_t g = (size_t)(b * LL + kt + row) * D3 + DD + h * DHH + ch * 8;
            cp16(s0 + (uint32_t)(row * 144 + ch * 16), qkv + g);
        }
        CP_COMMIT();
    };
    auto load_v = [&](int kt) {
        uint32_t s0 = sb + AOFF_V;
        #pragma unroll
        for (int u = 0; u < 4; u++) {
            int c = tid + u * 128;
            int row = c >> 3, ch = c & 7;
            size_t g = (size_t)(b * LL + kt + row) * D3 + 2 * DD + h * DHH + ch * 8;
            cp16(s0 + (uint32_t)(row * 144 + ch * 16), qkv + g);
        }
        CP_COMMIT();
    };

    // ---- prologue ----
    {
        int lr = tid >> 1, lc = (tid & 1) * 32;
        size_t gq = (size_t)(b * LL + q0 + lr) * D3 + h * DHH + lc;
        #pragma unroll
        for (int j = 0; j < 4; j++)
            *(uint4*)&Qh[lr * ATSTRIDE + lc + 8*j] = *(const uint4*)(qkv + gq + 8*j);
    }
    load_k(0, 0);
    if (tid < 64)
        maskadd[tid] = (1.0f - (float)mask[b * LL + tid]) * (-1e30f);
    __syncthreads();

    // ---- persistent Q fragments ----
    const uint32_t aoff = (uint32_t)(((lane & 15) * ATSTRIDE + ((lane >> 4) & 1) * 8) * 2);
    uint32_t qh[4][4];
    #pragma unroll
    for (int s = 0; s < 4; s++) {
        uint32_t ro = (uint32_t)((wid * 16) * 144) + (uint32_t)(s * 32);
        ldsm_x4(qh[s], sb + aoff + ro);
    }

    const uint32_t voff = (uint32_t)(((lane & 7) + 8 * ((lane >> 3) & 1)) * 144 + ((lane >> 4) & 1) * 16);

    float m0 = -1e30f, m1 = -1e30f, l0 = 0.f, l1 = 0.f;
    float o[8][4];
    #pragma unroll
    for (int j = 0; j < 8; j++)
        #pragma unroll
        for (int t = 0; t < 4; t++) o[j][t] = 0.f;

    for (int it = 0; it < LL / 64; it++) {
        const int kt = it * 64;
        const int bb = it & 1;
        CP_WAIT0();
        __syncthreads();
        load_v(kt);

        const uint32_t sKh = sb + (bb ? AOFF_K1 : AOFF_K0);

        // ---- S = Q K^T ----
        float s[8][4];
        #pragma unroll
        for (int j = 0; j < 8; j++)
            #pragma unroll
            for (int t = 0; t < 4; t++) s[j][t] = 0.f;
        #pragma unroll
        for (int ks = 0; ks < 4; ks++) {
            #pragma unroll
            for (int jp = 0; jp < 4; jp++) {
                uint32_t k4[4];
                uint32_t ro = (uint32_t)((16 * jp) * 144) + (uint32_t)(ks * 32);
                ldsm_x4(k4, sKh + aoff + ro);
                #pragma unroll
                for (int hf = 0; hf < 2; hf++) {
                    uint32_t bh[2] = { k4[hf], k4[hf + 2] };
                    mma_f16(s[2*jp + hf], qh[ks], bh);
                }
            }
        }

        // ---- online softmax ----
        float mx0 = -1e30f, mx1 = -1e30f;
        #pragma unroll
        for (int j = 0; j < 8; j++) {
            float ma0 = maskadd[bb * 64 + 8 * j + 2 * qc];
            float ma1 = maskadd[bb * 64 + 8 * j + 2 * qc + 1];
            s[j][0] = s[j][0] * 0.125f + ma0;
            s[j][1] = s[j][1] * 0.125f + ma1;
            s[j][2] = s[j][2] * 0.125f + ma0;
            s[j][3] = s[j][3] * 0.125f + ma1;
            mx0 = fmaxf(mx0, fmaxf(s[j][0], s[j][1]));
            mx1 = fmaxf(mx1, fmaxf(s[j][2], s[j][3]));
        }
        mx0 = fmaxf(mx0, __shfl_xor_sync(0xffffffffu, mx0, 1));
        mx0 = fmaxf(mx0, __shfl_xor_sync(0xffffffffu, mx0, 2));
        mx1 = fmaxf(mx1, __shfl_xor_sync(0xffffffffu, mx1, 1));
        mx1 = fmaxf(mx1, __shfl_xor_sync(0xffffffffu, mx1, 2));
        float mn0 = fmaxf(m0, mx0), mn1 = fmaxf(m1, mx1);
        float c0 = __expf(m0 - mn0), c1 = __expf(m1 - mn1);
        m0 = mn0; m1 = mn1;
        float ls0 = 0.f, ls1 = 0.f;
        #pragma unroll
        for (int j = 0; j < 8; j++) {
            s[j][0] = __expf(s[j][0] - mn0);
            s[j][1] = __expf(s[j][1] - mn0);
            s[j][2] = __expf(s[j][2] - mn1);
            s[j][3] = __expf(s[j][3] - mn1);
            ls0 += s[j][0] + s[j][1];
            ls1 += s[j][2] + s[j][3];
        }
        l0 = l0 * c0 + ls0;
        l1 = l1 * c1 + ls1;
        #pragma unroll
        for (int j = 0; j < 8; j++) {
            o[j][0] *= c0; o[j][1] *= c0;
            o[j][2] *= c1; o[j][3] *= c1;
        }

        CP_WAIT0();
        __syncthreads();
        if (it + 1 < LL / 64) {
            load_k(kt + 64, 1 - bb);
            if (tid < 64)
                maskadd[(1 - bb) * 64 + tid] =
                    (1.0f - (float)mask[b * LL + kt + 64 + tid]) * (-1e30f);
        }

        // ---- O += P @ V ----
        #pragma unroll
        for (int ks = 0; ks < 4; ks++) {
            uint32_t ph[4];
            __half2 p0 = __floats2half2_rn(s[2*ks][0],   s[2*ks][1]);
            __half2 p1 = __floats2half2_rn(s[2*ks][2],   s[2*ks][3]);
            __half2 p2 = __floats2half2_rn(s[2*ks+1][0], s[2*ks+1][1]);
            __half2 p3 = __floats2half2_rn(s[2*ks+1][2], s[2*ks+1][3]);
            ph[0] = *(uint32_t*)&p0; ph[1] = *(uint32_t*)&p1;
            ph[2] = *(uint32_t*)&p2; ph[3] = *(uint32_t*)&p3;
            uint32_t vbase = sb + AOFF_V + voff + (uint32_t)((16 * ks) * 144);
            #pragma unroll
            for (int jp = 0; jp < 4; jp++) {
                uint32_t v4[4];
                ldsm_x4_t(v4, vbase + (uint32_t)(32 * jp));
                mma_f16(o[2*jp],     ph, &v4[0]);
                mma_f16(o[2*jp + 1], ph, &v4[2]);
            }
        }
    }

    // ---- finalize ----
    l0 += __shfl_xor_sync(0xffffffffu, l0, 1);
    l0 += __shfl_xor_sync(0xffffffffu, l0, 2);
    l1 += __shfl_xor_sync(0xffffffffu, l1, 1);
    l1 += __shfl_xor_sync(0xffffffffu, l1, 2);
    float i0 = 1.0f / l0, i1 = 1.0f / l1;

    const int row0 = q0 + wid * 16 + er;
    #pragma unroll
    for (int j = 0; j < 8; j++) {
        int col = h * DHH + 8 * j + 2 * qc;
        size_t base0 = (size_t)(b * LL + row0) * DD + col;
        size_t base1 = base0 + 8 * (size_t)DD;
        float2 r0, r1;
        r0.x = o[j][0] * i0 + x[base0];
        r0.y = o[j][1] * i0 + x[base0 + 1];
        r1.x = o[j][2] * i1 + x[base1];
        r1.y = o[j][3] * i1 + x[base1 + 1];
        *(float2*)&res[base0] = r0;
        *(float2*)&res[base1] = r1;
    }
}

// ---------------- launch ----------------
extern "C" void kernel_launch(void* const* d_in, const int* in_sizes, int n_in,
                              void* d_out, int out_size)
{
    const float* x    = (const float*)d_in[0];
    const int*   mask = (const int*)  d_in[1];
    const float* Wq   = (const float*)d_in[2];
    const float* bq   = (const float*)d_in[3];
    const float* Wk   = (const float*)d_in[4];
    const float* bk   = (const float*)d_in[5];
    const float* Wv   = (const float*)d_in[6];
    const float* bv   = (const float*)d_in[7];
    const float* g1   = (const float*)d_in[8];
    const float* b1   = (const float*)d_in[9];
    const float* g2   = (const float*)d_in[10];
    const float* b2   = (const float*)d_in[11];
    const float* Wo1  = (const float*)d_in[12];
    const float* bo1  = (const float*)d_in[13];
    const float* Wo2  = (const float*)d_in[14];
    const float* bo2  = (const float*)d_in[15];
    float* out = (float*)d_out;

    __half *h_, *qkv_, *ln2_, *mlp_, *wqkv_, *w1_, *w2_;
    float *res_, *bqkv;
    cudaGetSymbolAddress((void**)&h_,    g_h);
    cudaGetSymbolAddress((void**)&qkv_,  g_qkv);
    cudaGetSymbolAddress((void**)&ln2_,  g_ln2);
    cudaGetSymbolAddress((void**)&mlp_,  g_mlp);
    cudaGetSymbolAddress((void**)&wqkv_, g_wqkv);
    cudaGetSymbolAddress((void**)&w1_,   g_w1);
    cudaGetSymbolAddress((void**)&w2_,   g_w2);
    cudaGetSymbolAddress((void**)&res_,  g_res);
    cudaGetSymbolAddress((void**)&bqkv,  g_bqkv);

    cudaFuncSetAttribute(hgemm_kernel<0, false, 2>, cudaFuncAttributeMaxDynamicSharedMemorySize, HGEMM_SMEM);
    cudaFuncSetAttribute(hgemm_kernel<1, false, 2>, cudaFuncAttributeMaxDynamicSharedMemorySize, HGEMM_SMEM);
    cudaFuncSetAttribute(hgemm_kernel<0, true,  0>, cudaFuncAttributeMaxDynamicSharedMemorySize, HGEMM_SMEM);
    cudaFuncSetAttribute(attn_mma_kernel, cudaFuncAttributeMaxDynamicSharedMemorySize, ATT2_SMEM);

    // 0) weight prep + bias concat
    wprep_kernel<<<dim3(32, 32, 5), dim3(32, 8)>>>(Wq, Wk, Wv, Wo1, Wo2, wqkv_, w1_, w2_);
    cudaMemcpyAsync(bqkv,        bq, DD * sizeof(float), cudaMemcpyDeviceToDevice, 0);
    cudaMemcpyAsync(bqkv + DD,   bk, DD * sizeof(float), cudaMemcpyDeviceToDevice, 0);
    cudaMemcpyAsync(bqkv + 2*DD, bv, DD * sizeof(float), cudaMemcpyDeviceToDevice, 0);

    // 1) LN1 -> fp16
    ln_half_kernel<<<NTOK, 256>>>(x, g1, b1, h_);

    // 2) fused QKV projection -> packed qkv fp16
    hgemm_kernel<0, false, 2><<<dim3(D3 / 128, NTOK / 128), 256, HGEMM_SMEM>>>(
        h_, wqkv_, bqkv, nullptr, nullptr, qkv_, NTOK, D3, DD);

    // 3) flash attention + residual -> res (fp32)
    attn_mma_kernel<<<dim3(LL / 64, BB * HH), 128, ATT2_SMEM>>>(qkv_, mask, x, res_);

    // 4) LN2 -> fp16
    ln_half_kernel<<<NTOK, 256>>>(res_, g2, b2, ln2_);

    // 5) MLP up + GELU -> fp16
    hgemm_kernel<1, false, 2><<<dim3(DD / 128, NTOK / 128), 256, HGEMM_SMEM>>>(
        ln2_, w1_, bo1, nullptr, nullptr, mlp_, NTOK, DD, DD);

    // 6) MLP down + bias + residual -> out (fp32)
    hgemm_kernel<0, true, 0><<<dim3(DD / 128, NTOK / 128), 256, HGEMM_SMEM>>>(
        mlp_, w2_, bo2, res_, out, nullptr, NTOK, DD, DD);
}

// round 15
// speedup vs baseline: 1.0899x; 1.0001x over previous
#include <cuda_runtime.h>
#include <cuda.h>
#include <cuda_fp16.h>
#include <math.h>
#include <stdint.h>

#define BB 4
#define LL 2048
#define DD 1024
#define HH 16
#define DHH 64
#define NTOK (BB*LL)   // 8192 rows
#define D3  (3*DD)     // 3072

// ---------------- scratch (device globals; no allocation allowed) ----------------
__device__ __align__(16) __half g_h   [NTOK*DD];
__device__ __align__(16) __half g_qkv [NTOK*D3];
__device__ __align__(16) __half g_ln2 [NTOK*DD];
__device__ __align__(16) __half g_mlp [NTOK*DD];
__device__ __align__(16) __half g_wqkv[3*DD*DD];
__device__ __align__(16) __half g_w1  [DD*DD];
__device__ __align__(16) __half g_w2  [DD*DD];
__device__ __align__(16) float  g_res [NTOK*DD];
__device__ __align__(16) float  g_bqkv[D3];

// ============================ helpers ============================
__device__ __forceinline__ uint32_t smem_u32(const void* p) {
    uint32_t a;
    asm("{ .reg .u64 t; cvta.to.shared.u64 t, %1; cvt.u32.u64 %0, t; }" : "=r"(a) : "l"(p));
    return a;
}
__device__ __forceinline__ void mma_f16(float* c, const uint32_t* a, const uint32_t* b) {
    asm volatile(
        "mma.sync.aligned.m16n8k16.row.col.f32.f16.f16.f32 "
        "{%0,%1,%2,%3}, {%4,%5,%6,%7}, {%8,%9}, {%0,%1,%2,%3};"
        : "+f"(c[0]), "+f"(c[1]), "+f"(c[2]), "+f"(c[3])
        : "r"(a[0]), "r"(a[1]), "r"(a[2]), "r"(a[3]), "r"(b[0]), "r"(b[1]));
}
__device__ __forceinline__ void ldsm_x4(uint32_t* r, uint32_t addr) {
    asm volatile("ldmatrix.sync.aligned.m8n8.x4.shared.b16 {%0,%1,%2,%3}, [%4];"
        : "=r"(r[0]), "=r"(r[1]), "=r"(r[2]), "=r"(r[3]) : "r"(addr));
}
__device__ __forceinline__ void ldsm_x4_t(uint32_t* r, uint32_t addr) {
    asm volatile("ldmatrix.sync.aligned.m8n8.x4.trans.shared.b16 {%0,%1,%2,%3}, [%4];"
        : "=r"(r[0]), "=r"(r[1]), "=r"(r[2]), "=r"(r[3]) : "r"(addr));
}
__device__ __forceinline__ void cp16(uint32_t dst, const void* src) {
    asm volatile("cp.async.cg.shared.global [%0], [%1], 16;" :: "r"(dst), "l"(src));
}
#define CP_COMMIT() asm volatile("cp.async.commit_group;" ::: "memory")
#define CP_WAIT0()  asm volatile("cp.async.wait_group 0;" ::: "memory")

// ============ fp16 GEMM, fp32 accum, BK=64 double-buffered (R13/R14 best) ============
#define GS_STRIDE 72                      // halfs per smem row (144B)
#define GT_BYTES  (128*GS_STRIDE*2)       // 18432 per tensor
#define GSTAGE    (2*GT_BYTES)            // A + B = 36864
#define HGEMM_SMEM (2*GSTAGE)             // 73728

template<int ACT, bool RES, int OUTM>
__global__ void __launch_bounds__(256, 2)
hgemm_kernel(const __half* __restrict__ A, const __half* __restrict__ B,
             const float* __restrict__ bias, const float* __restrict__ res,
             float* __restrict__ Cf, __half* __restrict__ Ch,
             int M, int N, int K)
{
    extern __shared__ char dsm[];
    const uint32_t sb = smem_u32(dsm);

    const int tid  = threadIdx.x;
    const int wid  = tid >> 5;
    const int lane = tid & 31;
    const int wm   = wid >> 2;
    const int wn   = wid & 3;
    const int row0 = blockIdx.y * 128;
    const int col0 = blockIdx.x * 128;

    float acc[4][4][4];
    #pragma unroll
    for (int i = 0; i < 4; i++)
        #pragma unroll
        for (int j = 0; j < 4; j++)
            #pragma unroll
            for (int q = 0; q < 4; q++) acc[i][j][q] = 0.f;

    const uint32_t aoff = (uint32_t)(((lane & 15) * GS_STRIDE + ((lane >> 4) & 1) * 8) * 2);
    const int nkt = K / 64;

    auto load_stage = [&](int i, int buf) {
        uint32_t s0 = sb + (uint32_t)buf * GSTAGE;
        int kt = i * 64;
        #pragma unroll
        for (int u = 0; u < 4; u++) {
            int c   = tid + u * 256;
            int row = c >> 3;
            int ch  = c & 7;
            uint32_t so = (uint32_t)(row * (GS_STRIDE * 2) + ch * 16);
            cp16(s0 + so,            A + (size_t)(row0 + row) * K + kt + ch * 8);
            cp16(s0 + GT_BYTES + so, B + (size_t)(col0 + row) * K + kt + ch * 8);
        }
        CP_COMMIT();
    };

    load_stage(0, 0);
    for (int i = 0; i < nkt; i++) {
        const int b = i & 1;
        CP_WAIT0();
        __syncthreads();
        if (i + 1 < nkt) load_stage(i + 1, 1 - b);
        const uint32_t sA = sb + (uint32_t)b * GSTAGE;
        const uint32_t sB = sA + GT_BYTES;
        #pragma unroll
        for (int ks = 0; ks < 64; ks += 16) {
            uint32_t ah[4][4];
            #pragma unroll
            for (int mt = 0; mt < 4; mt++) {
                uint32_t ro = (uint32_t)((wm * 64 + mt * 16) * (GS_STRIDE * 2)) + (uint32_t)(ks * 2);
                ldsm_x4(ah[mt], sA + aoff + ro);
            }
            #pragma unroll
            for (int ntp = 0; ntp < 2; ntp++) {
                uint32_t b4[4];
                uint32_t ro = (uint32_t)((wn * 32 + ntp * 16) * (GS_STRIDE * 2)) + (uint32_t)(ks * 2);
                ldsm_x4(b4, sB + aoff + ro);
                #pragma unroll
                for (int hfn = 0; hfn < 2; hfn++) {
                    int nt = ntp * 2 + hfn;
                    uint32_t bh[2] = { b4[hfn], b4[hfn + 2] };
                    #pragma unroll
                    for (int mt = 0; mt < 4; mt++)
                        mma_f16(acc[mt][nt], ah[mt], bh);
                }
            }
        }
    }

    const int er = lane >> 2;
    const int ec = (lane & 3) * 2;
    #pragma unroll
    for (int mt = 0; mt < 4; mt++) {
        #pragma unroll
        for (int half = 0; half < 2; half++) {
            int row = row0 + wm * 64 + mt * 16 + er + half * 8;
            #pragma unroll
            for (int nt = 0; nt < 4; nt++) {
                int col = col0 + wn * 32 + nt * 8 + ec;
                float v0 = acc[mt][nt][half * 2 + 0] + bias[col];
                float v1 = acc[mt][nt][half * 2 + 1] + bias[col + 1];
                if (ACT == 1) {
                    v0 = 0.5f * v0 * (1.0f + erff(v0 * 0.70710678118654752f));
                    v1 = 0.5f * v1 * (1.0f + erff(v1 * 0.70710678118654752f));
                }
                if (RES) {
                    const float* rp = res + (size_t)row * N;
                    v0 += rp[col]; v1 += rp[col + 1];
                }
                if (OUTM == 0) {
                    float2 o; o.x = v0; o.y = v1;
                    *(float2*)(Cf + (size_t)row * N + col) = o;
                } else {
                    __half2 h2 = __floats2half2_rn(v0, v1);
                    *(__half2*)(Ch + (size_t)row * N + col) = h2;
                }
            }
        }
    }
}

// ---------------- batched weight prep + bias concat (z=5 slice does biases) ----------------
__global__ void __launch_bounds__(256)
wprep_kernel(const float* __restrict__ Wq,  const float* __restrict__ Wk,
             const float* __restrict__ Wv,  const float* __restrict__ Wo1,
             const float* __restrict__ Wo2,
             const float* __restrict__ bq,  const float* __restrict__ bk,
             const float* __restrict__ bv,
             __half* __restrict__ wqkv, __half* __restrict__ w1,
             __half* __restrict__ w2,   float* __restrict__ bqkv)
{
    if (blockIdx.z == 5) {
        // bias concat: 3072 floats over 32x32 grid slice -> only use first 12 blocks
        int bi = blockIdx.y * 32 + blockIdx.x;
        int tid = threadIdx.y * 32 + threadIdx.x;
        int idx = bi * 256 + tid;
        if (idx < D3) {
            float v;
            if (idx < DD)            v = bq[idx];
            else if (idx < 2 * DD)   v = bk[idx - DD];
            else                     v = bv[idx - 2 * DD];
            bqkv[idx] = v;
        }
        return;
    }
    const float* in;
    __half* out;
    switch (blockIdx.z) {
        case 0: in = Wq;  out = wqkv;                        break;
        case 1: in = Wk;  out = wqkv + 1 * (size_t)DD * DD;  break;
        case 2: in = Wv;  out = wqkv + 2 * (size_t)DD * DD;  break;
        case 3: in = Wo1; out = w1;                          break;
        default: in = Wo2; out = w2;                         break;
    }
    __shared__ float t[32][33];
    int bx = blockIdx.x * 32, by = blockIdx.y * 32;
    int x = bx + threadIdx.x;
    #pragma unroll
    for (int j = 0; j < 32; j += 8)
        t[threadIdx.y + j][threadIdx.x] = in[(size_t)(by + threadIdx.y + j) * DD + x];
    __syncthreads();
    int x2 = by + threadIdx.x;
    #pragma unroll
    for (int j = 0; j < 32; j += 8)
        out[(size_t)(bx + threadIdx.y + j) * DD + x2] = __float2half(t[threadIdx.x][threadIdx.y + j]);
}

// ---------------- LayerNorm -> fp16, 2 rows per 256-thread block ----------------
__global__ void __launch_bounds__(256)
ln_half_kernel(const float* __restrict__ in, const float* __restrict__ gam,
               const float* __restrict__ bet, __half* __restrict__ oh)
{
    const int sub  = threadIdx.x >> 7;          // 0/1: which row of the pair
    const int t    = threadIdx.x & 127;         // 0..127 within row
    size_t base = ((size_t)blockIdx.x * 2 + sub) * DD;
    int t8 = t * 8;

    float4 va = *(const float4*)&in[base + t8];
    float4 vb = *(const float4*)&in[base + t8 + 4];
    float s  = va.x + va.y + va.z + va.w + vb.x + vb.y + vb.z + vb.w;
    float s2 = va.x*va.x + va.y*va.y + va.z*va.z + va.w*va.w
             + vb.x*vb.x + vb.y*vb.y + vb.z*vb.z + vb.w*vb.w;
    #pragma unroll
    for (int o = 16; o; o >>= 1) {
        s  += __shfl_xor_sync(0xffffffffu, s,  o);
        s2 += __shfl_xor_sync(0xffffffffu, s2, o);
    }
    __shared__ float rs[8], rs2[8];
    __shared__ float smu[2], srstd[2];
    int w = threadIdx.x >> 5, lane = threadIdx.x & 31;
    if (lane == 0) { rs[w] = s; rs2[w] = s2; }
    __syncthreads();
    if ((threadIdx.x & 127) == 0) {
        int w0 = sub * 4;
        float S = 0.f, S2 = 0.f;
        #pragma unroll
        for (int i = 0; i < 4; i++) { S += rs[w0 + i]; S2 += rs2[w0 + i]; }
        float mu  = S * (1.0f / DD);
        float var = S2 * (1.0f / DD) - mu * mu;
        smu[sub]   = mu;
        srstd[sub] = rsqrtf(var + 1e-6f);
    }
    __syncthreads();
    float mu = smu[sub], rstd = srstd[sub];
    float4 ga = *(const float4*)&gam[t8];
    float4 gb = *(const float4*)&gam[t8 + 4];
    float4 ba = *(const float4*)&bet[t8];
    float4 bb = *(const float4*)&bet[t8 + 4];
    __half2 h0 = __floats2half2_rn((va.x - mu) * rstd * ga.x + ba.x,
                                   (va.y - mu) * rstd * ga.y + ba.y);
    __half2 h1 = __floats2half2_rn((va.z - mu) * rstd * ga.z + ba.z,
                                   (va.w - mu) * rstd * ga.w + ba.w);
    __half2 h2 = __floats2half2_rn((vb.x - mu) * rstd * gb.x + bb.x,
                                   (vb.y - mu) * rstd * gb.y + bb.y);
    __half2 h3 = __floats2half2_rn((vb.z - mu) * rstd * gb.z + bb.z,
                                   (vb.w - mu) * rstd * gb.w + bb.w);
    *(__half2*)(oh + base + t8)     = h0;
    *(__half2*)(oh + base + t8 + 2) = h1;
    *(__half2*)(oh + base + t8 + 4) = h2;
    *(__half2*)(oh + base + t8 + 6) = h3;
}

// ============ fp16 flash attention (R10/R14 structure: K dbl-buf, V single) ============
#define ATSTRIDE 72
#define ATEN_BYTES (64*ATSTRIDE*2)   // 9216 per tensor
#define AOFF_K0 9216
#define AOFF_K1 18432
#define AOFF_V  27648
#define AOFF_M  36864
#define ATT2_SMEM (AOFF_M + 2*64*4)  // 37376

__global__ void __launch_bounds__(128, 4)
attn_mma_kernel(const __half* __restrict__ qkv,
                const int* __restrict__ mask,
                const float* __restrict__ x, float* __restrict__ res)
{
    extern __shared__ char sm8[];
    const uint32_t sb = smem_u32(sm8);
    __half* Qh = (__half*)sm8;
    float* maskadd = (float*)(sm8 + AOFF_M);

    const int tid  = threadIdx.x;
    const int wid  = tid >> 5;
    const int lane = tid & 31;
    const int b    = blockIdx.y >> 4;
    const int h    = blockIdx.y & 15;
    const int q0   = blockIdx.x * 64;
    const int er   = lane >> 2;
    const int qc   = lane & 3;

    auto load_k = [&](int kt, int buf) {
        uint32_t s0 = sb + (buf ? AOFF_K1 : AOFF_K0);
        #pragma unroll
        for (int u = 0; u < 4; u++) {
            int c = tid + u * 128;
            int row = c >> 3, ch = c & 7;
            size_t g = (size_t)(b * LL + kt + row) * D3 + DD + h * DHH + ch * 8;
            cp16(s0 + (uint32_t)(row * 144 + ch * 16), qkv + g);
        }
        CP_COMMIT();
    };
    auto load_v = [&](int kt) {
        uint32_t s0 = sb + AOFF_V;
        #pragma unroll
        for (int u = 0; u < 4; u++) {
            int c = tid + u * 128;
            int row = c >> 3, ch = c & 7;
            size_t g = (size_t)(b * LL + kt + row) * D3 + 2 * DD + h * DHH + ch * 8;
            cp16(s0 + (uint32_t)(row * 144 + ch * 16), qkv + g);
        }
        CP_COMMIT();
    };

    // ---- prologue ----
    {
        int lr = tid >> 1, lc = (tid & 1) * 32;
        size_t gq = (size_t)(b * LL + q0 + lr) * D3 + h * DHH + lc;
        #pragma unroll
        for (int j = 0; j < 4; j++)
            *(uint4*)&Qh[lr * ATSTRIDE + lc + 8*j] = *(const uint4*)(qkv + gq + 8*j);
    }
    load_k(0, 0);
    if (tid < 64)
        maskadd[tid] = (1.0f - (float)mask[b * LL + tid]) * (-1e30f);
    __syncthreads();

    // ---- persistent Q fragments ----
    const uint32_t aoff = (uint32_t)(((lane & 15) * ATSTRIDE + ((lane >> 4) & 1) * 8) * 2);
    uint32_t qh[4][4];
    #pragma unroll
    for (int s = 0; s < 4; s++) {
        uint32_t ro = (uint32_t)((wid * 16) * 144) + (uint32_t)(s * 32);
        ldsm_x4(qh[s], sb + aoff + ro);
    }

    const uint32_t voff = (uint32_t)(((lane & 7) + 8 * ((lane >> 3) & 1)) * 144 + ((lane >> 4) & 1) * 16);

    float m0 = -1e30f, m1 = -1e30f, l0 = 0.f, l1 = 0.f;
    float o[8][4];
    #pragma unroll
    for (int j = 0; j < 8; j++)
        #pragma unroll
        for (int t = 0; t < 4; t++) o[j][t] = 0.f;

    for (int it = 0; it < LL / 64; it++) {
        const int kt = it * 64;
        const int bb = it & 1;
        CP_WAIT0();
        __syncthreads();
        load_v(kt);

        const uint32_t sKh = sb + (bb ? AOFF_K1 : AOFF_K0);

        // ---- S = Q K^T ----
        float s[8][4];
        #pragma unroll
        for (int j = 0; j < 8; j++)
            #pragma unroll
            for (int t = 0; t < 4; t++) s[j][t] = 0.f;
        #pragma unroll
        for (int ks = 0; ks < 4; ks++) {
            #pragma unroll
            for (int jp = 0; jp < 4; jp++) {
                uint32_t k4[4];
                uint32_t ro = (uint32_t)((16 * jp) * 144) + (uint32_t)(ks * 32);
                ldsm_x4(k4, sKh + aoff + ro);
                #pragma unroll
                for (int hf = 0; hf < 2; hf++) {
                    uint32_t bh[2] = { k4[hf], k4[hf + 2] };
                    mma_f16(s[2*jp + hf], qh[ks], bh);
                }
            }
        }

        // ---- online softmax ----
        float mx0 = -1e30f, mx1 = -1e30f;
        #pragma unroll
        for (int j = 0; j < 8; j++) {
            float ma0 = maskadd[bb * 64 + 8 * j + 2 * qc];
            float ma1 = maskadd[bb * 64 + 8 * j + 2 * qc + 1];
            s[j][0] = s[j][0] * 0.125f + ma0;
            s[j][1] = s[j][1] * 0.125f + ma1;
            s[j][2] = s[j][2] * 0.125f + ma0;
            s[j][3] = s[j][3] * 0.125f + ma1;
            mx0 = fmaxf(mx0, fmaxf(s[j][0], s[j][1]));
            mx1 = fmaxf(mx1, fmaxf(s[j][2], s[j][3]));
        }
        mx0 = fmaxf(mx0, __shfl_xor_sync(0xffffffffu, mx0, 1));
        mx0 = fmaxf(mx0, __shfl_xor_sync(0xffffffffu, mx0, 2));
        mx1 = fmaxf(mx1, __shfl_xor_sync(0xffffffffu, mx1, 1));
        mx1 = fmaxf(mx1, __shfl_xor_sync(0xffffffffu, mx1, 2));
        float mn0 = fmaxf(m0, mx0), mn1 = fmaxf(m1, mx1);
        float c0 = __expf(m0 - mn0), c1 = __expf(m1 - mn1);
        m0 = mn0; m1 = mn1;
        float ls0 = 0.f, ls1 = 0.f;
        #pragma unroll
        for (int j = 0; j < 8; j++) {
            s[j][0] = __expf(s[j][0] - mn0);
            s[j][1] = __expf(s[j][1] - mn0);
            s[j][2] = __expf(s[j][2] - mn1);
            s[j][3] = __expf(s[j][3] - mn1);
            ls0 += s[j][0] + s[j][1];
            ls1 += s[j][2] + s[j][3];
        }
        l0 = l0 * c0 + ls0;
        l1 = l1 * c1 + ls1;
        #pragma unroll
        for (int j = 0; j < 8; j++) {
            o[j][0] *= c0; o[j][1] *= c0;
            o[j][2] *= c1; o[j][3] *= c1;
        }

        CP_WAIT0();
        __syncthreads();
        if (it + 1 < LL / 64) {
            load_k(kt + 64, 1 - bb);
            if (tid < 64)
                maskadd[(1 - bb) * 64 + tid] =
                    (1.0f - (float)mask[b * LL + kt + 64 + tid]) * (-1e30f);
        }

        // ---- O += P @ V ----
        #pragma unroll
        for (int ks = 0; ks < 4; ks++) {
            uint32_t ph[4];
            __half2 p0 = __floats2half2_rn(s[2*ks][0],   s[2*ks][1]);
            __half2 p1 = __floats2half2_rn(s[2*ks][2],   s[2*ks][3]);
            __half2 p2 = __floats2half2_rn(s[2*ks+1][0], s[2*ks+1][1]);
            __half2 p3 = __floats2half2_rn(s[2*ks+1][2], s[2*ks+1][3]);
            ph[0] = *(uint32_t*)&p0; ph[1] = *(uint32_t*)&p1;
            ph[2] = *(uint32_t*)&p2; ph[3] = *(uint32_t*)&p3;
            uint32_t vbase = sb + AOFF_V + voff + (uint32_t)((16 * ks) * 144);
            #pragma unroll
            for (int jp = 0; jp < 4; jp++) {
                uint32_t v4[4];
                ldsm_x4_t(v4, vbase + (uint32_t)(32 * jp));
                mma_f16(o[2*jp],     ph, &v4[0]);
                mma_f16(o[2*jp + 1], ph, &v4[2]);
            }
        }
    }

    // ---- finalize ----
    l0 += __shfl_xor_sync(0xffffffffu, l0, 1);
    l0 += __shfl_xor_sync(0xffffffffu, l0, 2);
    l1 += __shfl_xor_sync(0xffffffffu, l1, 1);
    l1 += __shfl_xor_sync(0xffffffffu, l1, 2);
    float i0 = 1.0f / l0, i1 = 1.0f / l1;

    const int row0 = q0 + wid * 16 + er;
    #pragma unroll
    for (int j = 0; j < 8; j++) {
        int col = h * DHH + 8 * j + 2 * qc;
        size_t base0 = (size_t)(b * LL + row0) * DD + col;
        size_t base1 = base0 + 8 * (size_t)DD;
        float2 r0, r1;
        r0.x = o[j][0] * i0 + x[base0];
        r0.y = o[j][1] * i0 + x[base0 + 1];
        r1.x = o[j][2] * i1 + x[base1];
        r1.y = o[j][3] * i1 + x[base1 + 1];
        *(float2*)&res[base0] = r0;
        *(float2*)&res[base1] = r1;
    }
}

// ---------------- launch ----------------
extern "C" void kernel_launch(void* const* d_in, const int* in_sizes, int n_in,
                              void* d_out, int out_size)
{
    const float* x    = (const float*)d_in[0];
    const int*   mask = (const int*)  d_in[1];
    const float* Wq   = (const float*)d_in[2];
    const float* bq   = (const float*)d_in[3];
    const float* Wk   = (const float*)d_in[4];
    const float* bk   = (const float*)d_in[5];
    const float* Wv   = (const float*)d_in[6];
    const float* bv   = (const float*)d_in[7];
    const float* g1   = (const float*)d_in[8];
    const float* b1   = (const float*)d_in[9];
    const float* g2   = (const float*)d_in[10];
    const float* b2   = (const float*)d_in[11];
    const float* Wo1  = (const float*)d_in[12];
    const float* bo1  = (const float*)d_in[13];
    const float* Wo2  = (const float*)d_in[14];
    const float* bo2  = (const float*)d_in[15];
    float* out = (float*)d_out;

    __half *h_, *qkv_, *ln2_, *mlp_, *wqkv_, *w1_, *w2_;
    float *res_, *bqkv;
    cudaGetSymbolAddress((void**)&h_,    g_h);
    cudaGetSymbolAddress((void**)&qkv_,  g_qkv);
    cudaGetSymbolAddress((void**)&ln2_,  g_ln2);
    cudaGetSymbolAddress((void**)&mlp_,  g_mlp);
    cudaGetSymbolAddress((void**)&wqkv_, g_wqkv);
    cudaGetSymbolAddress((void**)&w1_,   g_w1);
    cudaGetSymbolAddress((void**)&w2_,   g_w2);
    cudaGetSymbolAddress((void**)&res_,  g_res);
    cudaGetSymbolAddress((void**)&bqkv,  g_bqkv);

    cudaFuncSetAttribute(hgemm_kernel<0, false, 2>, cudaFuncAttributeMaxDynamicSharedMemorySize, HGEMM_SMEM);
    cudaFuncSetAttribute(hgemm_kernel<1, false, 2>, cudaFuncAttributeMaxDynamicSharedMemorySize, HGEMM_SMEM);
    cudaFuncSetAttribute(hgemm_kernel<0, true,  0>, cudaFuncAttributeMaxDynamicSharedMemorySize, HGEMM_SMEM);
    cudaFuncSetAttribute(attn_mma_kernel, cudaFuncAttributeMaxDynamicSharedMemorySize, ATT2_SMEM);

    // 0) weight prep + bias concat (single launch, z=5 handles biases)
    wprep_kernel<<<dim3(32, 32, 6), dim3(32, 8)>>>(Wq, Wk, Wv, Wo1, Wo2,
                                                   bq, bk, bv, wqkv_, w1_, w2_, bqkv);

    // 1) LN1 -> fp16 (2 rows/block)
    ln_half_kernel<<<NTOK / 2, 256>>>(x, g1, b1, h_);

    // 2) fused QKV projection -> packed qkv fp16
    hgemm_kernel<0, false, 2><<<dim3(D3 / 128, NTOK / 128), 256, HGEMM_SMEM>>>(
        h_, wqkv_, bqkv, nullptr, nullptr, qkv_, NTOK, D3, DD);

    // 3) flash attention + residual -> res (fp32)
    attn_mma_kernel<<<dim3(LL / 64, BB * HH), 128, ATT2_SMEM>>>(qkv_, mask, x, res_);

    // 4) LN2 -> fp16 (2 rows/block)
    ln_half_kernel<<<NTOK / 2, 256>>>(res_, g2, b2, ln2_);

    // 5) MLP up + GELU -> fp16
    hgemm_kernel<1, false, 2><<<dim3(DD / 128, NTOK / 128), 256, HGEMM_SMEM>>>(
        ln2_, w1_, bo1, nullptr, nullptr, mlp_, NTOK, DD, DD);

    // 6) MLP down + bias + residual -> out (fp32)
    hgemm_kernel<0, true, 0><<<dim3(DD / 128, NTOK / 128), 256, HGEMM_SMEM>>>(
        mlp_, w2_, bo2, res_, out, nullptr, NTOK, DD, DD);
}

// round 16
// speedup vs baseline: 1.0943x; 1.0041x over previous
#include <cuda_runtime.h>
#include <cuda.h>
#include <cuda_fp16.h>
#include <math.h>
#include <stdint.h>

#define BB 4
#define LL 2048
#define DD 1024
#define HH 16
#define DHH 64
#define NTOK (BB*LL)   // 8192 rows
#define D3  (3*DD)     // 3072

// ---------------- scratch (device globals; no allocation allowed) ----------------
__device__ __align__(16) __half g_h   [NTOK*DD];
__device__ __align__(16) __half g_qkv [NTOK*D3];
__device__ __align__(16) __half g_ln2 [NTOK*DD];
__device__ __align__(16) __half g_mlp [NTOK*DD];
__device__ __align__(16) __half g_wqkv[3*DD*DD];
__device__ __align__(16) __half g_w1  [DD*DD];
__device__ __align__(16) __half g_w2  [DD*DD];
__device__ __align__(16) float  g_res [NTOK*DD];
__device__ __align__(16) float  g_bqkv[D3];

// ============================ helpers ============================
__device__ __forceinline__ uint32_t smem_u32(const void* p) {
    uint32_t a;
    asm("{ .reg .u64 t; cvta.to.shared.u64 t, %1; cvt.u32.u64 %0, t; }" : "=r"(a) : "l"(p));
    return a;
}
__device__ __forceinline__ void mma_f16(float* c, const uint32_t* a, const uint32_t* b) {
    asm volatile(
        "mma.sync.aligned.m16n8k16.row.col.f32.f16.f16.f32 "
        "{%0,%1,%2,%3}, {%4,%5,%6,%7}, {%8,%9}, {%0,%1,%2,%3};"
        : "+f"(c[0]), "+f"(c[1]), "+f"(c[2]), "+f"(c[3])
        : "r"(a[0]), "r"(a[1]), "r"(a[2]), "r"(a[3]), "r"(b[0]), "r"(b[1]));
}
__device__ __forceinline__ void ldsm_x4(uint32_t* r, uint32_t addr) {
    asm volatile("ldmatrix.sync.aligned.m8n8.x4.shared.b16 {%0,%1,%2,%3}, [%4];"
        : "=r"(r[0]), "=r"(r[1]), "=r"(r[2]), "=r"(r[3]) : "r"(addr));
}
__device__ __forceinline__ void ldsm_x4_t(uint32_t* r, uint32_t addr) {
    asm volatile("ldmatrix.sync.aligned.m8n8.x4.trans.shared.b16 {%0,%1,%2,%3}, [%4];"
        : "=r"(r[0]), "=r"(r[1]), "=r"(r[2]), "=r"(r[3]) : "r"(addr));
}
__device__ __forceinline__ void cp16(uint32_t dst, const void* src) {
    asm volatile("cp.async.cg.shared.global [%0], [%1], 16;" :: "r"(dst), "l"(src));
}
#define CP_COMMIT() asm volatile("cp.async.commit_group;" ::: "memory")
#define CP_WAIT0()  asm volatile("cp.async.wait_group 0;" ::: "memory")

// ============ fp16 GEMM, fp32 accum, BK=64 double-buffered ============
#define GS_STRIDE 72                      // halfs per smem row (144B)
#define GT_BYTES  (128*GS_STRIDE*2)       // 18432 per tensor
#define GSTAGE    (2*GT_BYTES)            // A + B = 36864
#define HGEMM_SMEM (2*GSTAGE)             // 73728

template<int ACT, bool RES, int OUTM>
__global__ void __launch_bounds__(256, 2)
hgemm_kernel(const __half* __restrict__ A, const __half* __restrict__ B,
             const float* __restrict__ bias, const float* __restrict__ res,
             float* __restrict__ Cf, __half* __restrict__ Ch,
             int M, int N, int K)
{
    extern __shared__ char dsm[];
    const uint32_t sb = smem_u32(dsm);

    const int tid  = threadIdx.x;
    const int wid  = tid >> 5;
    const int lane = tid & 31;
    const int wm   = wid >> 2;
    const int wn   = wid & 3;
    const int row0 = blockIdx.y * 128;
    const int col0 = blockIdx.x * 128;

    float acc[4][4][4];
    #pragma unroll
    for (int i = 0; i < 4; i++)
        #pragma unroll
        for (int j = 0; j < 4; j++)
            #pragma unroll
            for (int q = 0; q < 4; q++) acc[i][j][q] = 0.f;

    const uint32_t aoff = (uint32_t)(((lane & 15) * GS_STRIDE + ((lane >> 4) & 1) * 8) * 2);
    const int nkt = K / 64;

    auto load_stage = [&](int i, int buf) {
        uint32_t s0 = sb + (uint32_t)buf * GSTAGE;
        int kt = i * 64;
        #pragma unroll
        for (int u = 0; u < 4; u++) {
            int c   = tid + u * 256;
            int row = c >> 3;
            int ch  = c & 7;
            uint32_t so = (uint32_t)(row * (GS_STRIDE * 2) + ch * 16);
            cp16(s0 + so,            A + (size_t)(row0 + row) * K + kt + ch * 8);
            cp16(s0 + GT_BYTES + so, B + (size_t)(col0 + row) * K + kt + ch * 8);
        }
        CP_COMMIT();
    };

    load_stage(0, 0);
    for (int i = 0; i < nkt; i++) {
        const int b = i & 1;
        CP_WAIT0();
        __syncthreads();
        if (i + 1 < nkt) load_stage(i + 1, 1 - b);
        const uint32_t sA = sb + (uint32_t)b * GSTAGE;
        const uint32_t sB = sA + GT_BYTES;
        #pragma unroll
        for (int ks = 0; ks < 64; ks += 16) {
            uint32_t ah[4][4];
            #pragma unroll
            for (int mt = 0; mt < 4; mt++) {
                uint32_t ro = (uint32_t)((wm * 64 + mt * 16) * (GS_STRIDE * 2)) + (uint32_t)(ks * 2);
                ldsm_x4(ah[mt], sA + aoff + ro);
            }
            #pragma unroll
            for (int ntp = 0; ntp < 2; ntp++) {
                uint32_t b4[4];
                uint32_t ro = (uint32_t)((wn * 32 + ntp * 16) * (GS_STRIDE * 2)) + (uint32_t)(ks * 2);
                ldsm_x4(b4, sB + aoff + ro);
                #pragma unroll
                for (int hfn = 0; hfn < 2; hfn++) {
                    int nt = ntp * 2 + hfn;
                    uint32_t bh[2] = { b4[hfn], b4[hfn + 2] };
                    #pragma unroll
                    for (int mt = 0; mt < 4; mt++)
                        mma_f16(acc[mt][nt], ah[mt], bh);
                }
            }
        }
    }

    const int er = lane >> 2;
    const int ec = (lane & 3) * 2;
    #pragma unroll
    for (int mt = 0; mt < 4; mt++) {
        #pragma unroll
        for (int half = 0; half < 2; half++) {
            int row = row0 + wm * 64 + mt * 16 + er + half * 8;
            #pragma unroll
            for (int nt = 0; nt < 4; nt++) {
                int col = col0 + wn * 32 + nt * 8 + ec;
                float v0 = acc[mt][nt][half * 2 + 0] + bias[col];
                float v1 = acc[mt][nt][half * 2 + 1] + bias[col + 1];
                if (ACT == 1) {
                    v0 = 0.5f * v0 * (1.0f + erff(v0 * 0.70710678118654752f));
                    v1 = 0.5f * v1 * (1.0f + erff(v1 * 0.70710678118654752f));
                }
                if (RES) {
                    const float* rp = res + (size_t)row * N;
                    v0 += rp[col]; v1 += rp[col + 1];
                }
                if (OUTM == 0) {
                    float2 o; o.x = v0; o.y = v1;
                    *(float2*)(Cf + (size_t)row * N + col) = o;
                } else {
                    __half2 h2 = __floats2half2_rn(v0, v1);
                    *(__half2*)(Ch + (size_t)row * N + col) = h2;
                }
            }
        }
    }
}

// ---------------- LN row-pair body (256 threads, 2 rows) ----------------
__device__ __forceinline__ void ln_pair_body(
    const float* __restrict__ in, const float* __restrict__ gam,
    const float* __restrict__ bet, __half* __restrict__ oh,
    int pair, int ltid, float* rs, float* rs2, float* smu, float* srstd)
{
    const int sub = ltid >> 7;
    const int t   = ltid & 127;
    size_t base = ((size_t)pair * 2 + sub) * DD;
    int t8 = t * 8;

    float4 va = *(const float4*)&in[base + t8];
    float4 vb = *(const float4*)&in[base + t8 + 4];
    float s  = va.x + va.y + va.z + va.w + vb.x + vb.y + vb.z + vb.w;
    float s2 = va.x*va.x + va.y*va.y + va.z*va.z + va.w*va.w
             + vb.x*vb.x + vb.y*vb.y + vb.z*vb.z + vb.w*vb.w;
    #pragma unroll
    for (int o = 16; o; o >>= 1) {
        s  += __shfl_xor_sync(0xffffffffu, s,  o);
        s2 += __shfl_xor_sync(0xffffffffu, s2, o);
    }
    int w = ltid >> 5, lane = ltid & 31;
    if (lane == 0) { rs[w] = s; rs2[w] = s2; }
    __syncthreads();
    if ((ltid & 127) == 0) {
        int w0 = sub * 4;
        float S = 0.f, S2 = 0.f;
        #pragma unroll
        for (int i = 0; i < 4; i++) { S += rs[w0 + i]; S2 += rs2[w0 + i]; }
        float mu  = S * (1.0f / DD);
        float var = S2 * (1.0f / DD) - mu * mu;
        smu[sub]   = mu;
        srstd[sub] = rsqrtf(var + 1e-6f);
    }
    __syncthreads();
    float mu = smu[sub], rstd = srstd[sub];
    float4 ga = *(const float4*)&gam[t8];
    float4 gb = *(const float4*)&gam[t8 + 4];
    float4 ba = *(const float4*)&bet[t8];
    float4 bb = *(const float4*)&bet[t8 + 4];
    __half2 h0 = __floats2half2_rn((va.x - mu) * rstd * ga.x + ba.x,
                                   (va.y - mu) * rstd * ga.y + ba.y);
    __half2 h1 = __floats2half2_rn((va.z - mu) * rstd * ga.z + ba.z,
                                   (va.w - mu) * rstd * ga.w + ba.w);
    __half2 h2 = __floats2half2_rn((vb.x - mu) * rstd * gb.x + bb.x,
                                   (vb.y - mu) * rstd * gb.y + bb.y);
    __half2 h3 = __floats2half2_rn((vb.z - mu) * rstd * gb.z + bb.z,
                                   (vb.w - mu) * rstd * gb.w + bb.w);
    *(__half2*)(oh + base + t8)     = h0;
    *(__half2*)(oh + base + t8 + 2) = h1;
    *(__half2*)(oh + base + t8 + 4) = h2;
    *(__half2*)(oh + base + t8 + 6) = h3;
}

// ---------------- fused prep: weights (z 0-4) + bias (z 5) + LN1 (z 6-9) ----------------
__global__ void __launch_bounds__(256)
wprep_kernel(const float* __restrict__ Wq,  const float* __restrict__ Wk,
             const float* __restrict__ Wv,  const float* __restrict__ Wo1,
             const float* __restrict__ Wo2,
             const float* __restrict__ bq,  const float* __restrict__ bk,
             const float* __restrict__ bv,
             const float* __restrict__ x,   const float* __restrict__ g1,
             const float* __restrict__ b1,  __half* __restrict__ hout,
             __half* __restrict__ wqkv, __half* __restrict__ w1,
             __half* __restrict__ w2,   float* __restrict__ bqkv)
{
    const int z = blockIdx.z;
    if (z >= 6) {
        // LN1: 4096 row-pairs over z=6..9, 1024 blocks each
        __shared__ float rs[8], rs2[8], smu[2], srstd[2];
        int pair = (z - 6) * 1024 + blockIdx.y * 32 + blockIdx.x;
        int ltid = threadIdx.y * 32 + threadIdx.x;
        ln_pair_body(x, g1, b1, hout, pair, ltid, rs, rs2, smu, srstd);
        return;
    }
    if (z == 5) {
        int bi = blockIdx.y * 32 + blockIdx.x;
        int tid = threadIdx.y * 32 + threadIdx.x;
        int idx = bi * 256 + tid;
        if (idx < D3) {
            float v;
            if (idx < DD)            v = bq[idx];
            else if (idx < 2 * DD)   v = bk[idx - DD];
            else                     v = bv[idx - 2 * DD];
            bqkv[idx] = v;
        }
        return;
    }
    const float* in;
    __half* out;
    switch (z) {
        case 0: in = Wq;  out = wqkv;                        break;
        case 1: in = Wk;  out = wqkv + 1 * (size_t)DD * DD;  break;
        case 2: in = Wv;  out = wqkv + 2 * (size_t)DD * DD;  break;
        case 3: in = Wo1; out = w1;                          break;
        default: in = Wo2; out = w2;                         break;
    }
    __shared__ float t[32][33];
    int bx = blockIdx.x * 32, by = blockIdx.y * 32;
    int xx = bx + threadIdx.x;
    #pragma unroll
    for (int j = 0; j < 32; j += 8)
        t[threadIdx.y + j][threadIdx.x] = in[(size_t)(by + threadIdx.y + j) * DD + xx];
    __syncthreads();
    int x2 = by + threadIdx.x;
    #pragma unroll
    for (int j = 0; j < 32; j += 8)
        out[(size_t)(bx + threadIdx.y + j) * DD + x2] = __float2half(t[threadIdx.x][threadIdx.y + j]);
}

// ---------------- standalone LN (used for LN2) ----------------
__global__ void __launch_bounds__(256)
ln_half_kernel(const float* __restrict__ in, const float* __restrict__ gam,
               const float* __restrict__ bet, __half* __restrict__ oh)
{
    __shared__ float rs[8], rs2[8], smu[2], srstd[2];
    ln_pair_body(in, gam, bet, oh, blockIdx.x, threadIdx.x, rs, rs2, smu, srstd);
}

// ============ fp16 flash attention (K dbl-buf, V single; measured-best) ============
#define ATSTRIDE 72
#define ATEN_BYTES (64*ATSTRIDE*2)   // 9216 per tensor
#define AOFF_K0 9216
#define AOFF_K1 18432
#define AOFF_V  27648
#define AOFF_M  36864
#define ATT2_SMEM (AOFF_M + 2*64*4)  // 37376

__global__ void __launch_bounds__(128, 4)
attn_mma_kernel(const __half* __restrict__ qkv,
                const int* __restrict__ mask,
                const float* __restrict__ x, float* __restrict__ res)
{
    extern __shared__ char sm8[];
    const uint32_t sb = smem_u32(sm8);
    __half* Qh = (__half*)sm8;
    float* maskadd = (float*)(sm8 + AOFF_M);

    const int tid  = threadIdx.x;
    const int wid  = tid >> 5;
    const int lane = tid & 31;
    const int b    = blockIdx.y >> 4;
    const int h    = blockIdx.y & 15;
    const int q0   = blockIdx.x * 64;
    const int er   = lane >> 2;
    const int qc   = lane & 3;

    auto load_k = [&](int kt, int buf) {
        uint32_t s0 = sb + (buf ? AOFF_K1 : AOFF_K0);
        #pragma unroll
        for (int u = 0; u < 4; u++) {
            int c = tid + u * 128;
            int row = c >> 3, ch = c & 7;
            size_t g = (size_t)(b * LL + kt + row) * D3 + DD + h * DHH + ch * 8;
            cp16(s0 + (uint32_t)(row * 144 + ch * 16), qkv + g);
        }
        CP_COMMIT();
    };
    auto load_v = [&](int kt) {
        uint32_t s0 = sb + AOFF_V;
        #pragma unroll
        for (int u = 0; u < 4; u++) {
            int c = tid + u * 128;
            int row = c >> 3, ch = c & 7;
            size_t g = (size_t)(b * LL + kt + row) * D3 + 2 * DD + h * DHH + ch * 8;
            cp16(s0 + (uint32_t)(row * 144 + ch * 16), qkv + g);
        }
        CP_COMMIT();
    };

    // ---- prologue ----
    {
        int lr = tid >> 1, lc = (tid & 1) * 32;
        size_t gq = (size_t)(b * LL + q0 + lr) * D3 + h * DHH + lc;
        #pragma unroll
        for (int j = 0; j < 4; j++)
            *(uint4*)&Qh[lr * ATSTRIDE + lc + 8*j] = *(const uint4*)(qkv + gq + 8*j);
    }
    load_k(0, 0);
    if (tid < 64)
        maskadd[tid] = (1.0f - (float)mask[b * LL + tid]) * (-1e30f);
    __syncthreads();

    // ---- persistent Q fragments ----
    const uint32_t aoff = (uint32_t)(((lane & 15) * ATSTRIDE + ((lane >> 4) & 1) * 8) * 2);
    uint32_t qh[4][4];
    #pragma unroll
    for (int s = 0; s < 4; s++) {
        uint32_t ro = (uint32_t)((wid * 16) * 144) + (uint32_t)(s * 32);
        ldsm_x4(qh[s], sb + aoff + ro);
    }

    const uint32_t voff = (uint32_t)(((lane & 7) + 8 * ((lane >> 3) & 1)) * 144 + ((lane >> 4) & 1) * 16);

    float m0 = -1e30f, m1 = -1e30f, l0 = 0.f, l1 = 0.f;
    float o[8][4];
    #pragma unroll
    for (int j = 0; j < 8; j++)
        #pragma unroll
        for (int t = 0; t < 4; t++) o[j][t] = 0.f;

    for (int it = 0; it < LL / 64; it++) {
        const int kt = it * 64;
        const int bb = it & 1;
        CP_WAIT0();
        __syncthreads();
        load_v(kt);

        const uint32_t sKh = sb + (bb ? AOFF_K1 : AOFF_K0);

        // ---- S = Q K^T ----
        float s[8][4];
        #pragma unroll
        for (int j = 0; j < 8; j++)
            #pragma unroll
            for (int t = 0; t < 4; t++) s[j][t] = 0.f;
        #pragma unroll
        for (int ks = 0; ks < 4; ks++) {
            #pragma unroll
            for (int jp = 0; jp < 4; jp++) {
                uint32_t k4[4];
                uint32_t ro = (uint32_t)((16 * jp) * 144) + (uint32_t)(ks * 32);
                ldsm_x4(k4, sKh + aoff + ro);
                #pragma unroll
                for (int hf = 0; hf < 2; hf++) {
                    uint32_t bh[2] = { k4[hf], k4[hf + 2] };
                    mma_f16(s[2*jp + hf], qh[ks], bh);
                }
            }
        }

        // ---- online softmax ----
        float mx0 = -1e30f, mx1 = -1e30f;
        #pragma unroll
        for (int j = 0; j < 8; j++) {
            float ma0 = maskadd[bb * 64 + 8 * j + 2 * qc];
            float ma1 = maskadd[bb * 64 + 8 * j + 2 * qc + 1];
            s[j][0] = s[j][0] * 0.125f + ma0;
            s[j][1] = s[j][1] * 0.125f + ma1;
            s[j][2] = s[j][2] * 0.125f + ma0;
            s[j][3] = s[j][3] * 0.125f + ma1;
            mx0 = fmaxf(mx0, fmaxf(s[j][0], s[j][1]));
            mx1 = fmaxf(mx1, fmaxf(s[j][2], s[j][3]));
        }
        mx0 = fmaxf(mx0, __shfl_xor_sync(0xffffffffu, mx0, 1));
        mx0 = fmaxf(mx0, __shfl_xor_sync(0xffffffffu, mx0, 2));
        mx1 = fmaxf(mx1, __shfl_xor_sync(0xffffffffu, mx1, 1));
        mx1 = fmaxf(mx1, __shfl_xor_sync(0xffffffffu, mx1, 2));
        float mn0 = fmaxf(m0, mx0), mn1 = fmaxf(m1, mx1);
        float c0 = __expf(m0 - mn0), c1 = __expf(m1 - mn1);
        m0 = mn0; m1 = mn1;
        float ls0 = 0.f, ls1 = 0.f;
        #pragma unroll
        for (int j = 0; j < 8; j++) {
            s[j][0] = __expf(s[j][0] - mn0);
            s[j][1] = __expf(s[j][1] - mn0);
            s[j][2] = __expf(s[j][2] - mn1);
            s[j][3] = __expf(s[j][3] - mn1);
            ls0 += s[j][0] + s[j][1];
            ls1 += s[j][2] + s[j][3];
        }
        l0 = l0 * c0 + ls0;
        l1 = l1 * c1 + ls1;
        #pragma unroll
        for (int j = 0; j < 8; j++) {
            o[j][0] *= c0; o[j][1] *= c0;
            o[j][2] *= c1; o[j][3] *= c1;
        }

        CP_WAIT0();
        __syncthreads();
        if (it + 1 < LL / 64) {
            load_k(kt + 64, 1 - bb);
            if (tid < 64)
                maskadd[(1 - bb) * 64 + tid] =
                    (1.0f - (float)mask[b * LL + kt + 64 + tid]) * (-1e30f);
        }

        // ---- O += P @ V ----
        #pragma unroll
        for (int ks = 0; ks < 4; ks++) {
            uint32_t ph[4];
            __half2 p0 = __floats2half2_rn(s[2*ks][0],   s[2*ks][1]);
            __half2 p1 = __floats2half2_rn(s[2*ks][2],   s[2*ks][3]);
            __half2 p2 = __floats2half2_rn(s[2*ks+1][0], s[2*ks+1][1]);
            __half2 p3 = __floats2half2_rn(s[2*ks+1][2], s[2*ks+1][3]);
            ph[0] = *(uint32_t*)&p0; ph[1] = *(uint32_t*)&p1;
            ph[2] = *(uint32_t*)&p2; ph[3] = *(uint32_t*)&p3;
            uint32_t vbase = sb + AOFF_V + voff + (uint32_t)((16 * ks) * 144);
            #pragma unroll
            for (int jp = 0; jp < 4; jp++) {
                uint32_t v4[4];
                ldsm_x4_t(v4, vbase + (uint32_t)(32 * jp));
                mma_f16(o[2*jp],     ph, &v4[0]);
                mma_f16(o[2*jp + 1], ph, &v4[2]);
            }
        }
    }

    // ---- finalize ----
    l0 += __shfl_xor_sync(0xffffffffu, l0, 1);
    l0 += __shfl_xor_sync(0xffffffffu, l0, 2);
    l1 += __shfl_xor_sync(0xffffffffu, l1, 1);
    l1 += __shfl_xor_sync(0xffffffffu, l1, 2);
    float i0 = 1.0f / l0, i1 = 1.0f / l1;

    const int row0 = q0 + wid * 16 + er;
    #pragma unroll
    for (int j = 0; j < 8; j++) {
        int col = h * DHH + 8 * j + 2 * qc;
        size_t base0 = (size_t)(b * LL + row0) * DD + col;
        size_t base1 = base0 + 8 * (size_t)DD;
        float2 r0, r1;
        r0.x = o[j][0] * i0 + x[base0];
        r0.y = o[j][1] * i0 + x[base0 + 1];
        r1.x = o[j][2] * i1 + x[base1];
        r1.y = o[j][3] * i1 + x[base1 + 1];
        *(float2*)&res[base0] = r0;
        *(float2*)&res[base1] = r1;
    }
}

// ---------------- launch ----------------
extern "C" void kernel_launch(void* const* d_in, const int* in_sizes, int n_in,
                              void* d_out, int out_size)
{
    const float* x    = (const float*)d_in[0];
    const int*   mask = (const int*)  d_in[1];
    const float* Wq   = (const float*)d_in[2];
    const float* bq   = (const float*)d_in[3];
    const float* Wk   = (const float*)d_in[4];
    const float* bk   = (const float*)d_in[5];
    const float* Wv   = (const float*)d_in[6];
    const float* bv   = (const float*)d_in[7];
    const float* g1   = (const float*)d_in[8];
    const float* b1   = (const float*)d_in[9];
    const float* g2   = (const float*)d_in[10];
    const float* b2   = (const float*)d_in[11];
    const float* Wo1  = (const float*)d_in[12];
    const float* bo1  = (const float*)d_in[13];
    const float* Wo2  = (const float*)d_in[14];
    const float* bo2  = (const float*)d_in[15];
    float* out = (float*)d_out;

    __half *h_, *qkv_, *ln2_, *mlp_, *wqkv_, *w1_, *w2_;
    float *res_, *bqkv;
    cudaGetSymbolAddress((void**)&h_,    g_h);
    cudaGetSymbolAddress((void**)&qkv_,  g_qkv);
    cudaGetSymbolAddress((void**)&ln2_,  g_ln2);
    cudaGetSymbolAddress((void**)&mlp_,  g_mlp);
    cudaGetSymbolAddress((void**)&wqkv_, g_wqkv);
    cudaGetSymbolAddress((void**)&w1_,   g_w1);
    cudaGetSymbolAddress((void**)&w2_,   g_w2);
    cudaGetSymbolAddress((void**)&res_,  g_res);
    cudaGetSymbolAddress((void**)&bqkv,  g_bqkv);

    cudaFuncSetAttribute(hgemm_kernel<0, false, 2>, cudaFuncAttributeMaxDynamicSharedMemorySize, HGEMM_SMEM);
    cudaFuncSetAttribute(hgemm_kernel<1, false, 2>, cudaFuncAttributeMaxDynamicSharedMemorySize, HGEMM_SMEM);
    cudaFuncSetAttribute(hgemm_kernel<0, true,  0>, cudaFuncAttributeMaxDynamicSharedMemorySize, HGEMM_SMEM);
    cudaFuncSetAttribute(attn_mma_kernel, cudaFuncAttributeMaxDynamicSharedMemorySize, ATT2_SMEM);

    // 0+1) fused prep: weight transpose + bias concat + LN1 (single launch)
    wprep_kernel<<<dim3(32, 32, 10), dim3(32, 8)>>>(Wq, Wk, Wv, Wo1, Wo2,
                                                    bq, bk, bv, x, g1, b1, h_,
                                                    wqkv_, w1_, w2_, bqkv);

    // 2) fused QKV projection -> packed qkv fp16
    hgemm_kernel<0, false, 2><<<dim3(D3 / 128, NTOK / 128), 256, HGEMM_SMEM>>>(
        h_, wqkv_, bqkv, nullptr, nullptr, qkv_, NTOK, D3, DD);

    // 3) flash attention + residual -> res (fp32)
    attn_mma_kernel<<<dim3(LL / 64, BB * HH), 128, ATT2_SMEM>>>(qkv_, mask, x, res_);

    // 4) LN2 -> fp16 (2 rows/block)
    ln_half_kernel<<<NTOK / 2, 256>>>(res_, g2, b2, ln2_);

    // 5) MLP up + GELU -> fp16
    hgemm_kernel<1, false, 2><<<dim3(DD / 128, NTOK / 128), 256, HGEMM_SMEM>>>(
        ln2_, w1_, bo1, nullptr, nullptr, mlp_, NTOK, DD, DD);

    // 6) MLP down + bias + residual -> out (fp32)
    hgemm_kernel<0, true, 0><<<dim3(DD / 128, NTOK / 128), 256, HGEMM_SMEM>>>(
        mlp_, w2_, bo2, res_, out, nullptr, NTOK, DD, DD);
}